// round 1
// baseline (speedup 1.0000x reference)
#include <cuda_runtime.h>
#include <cuda_bf16.h>
#include <math.h>

// ---------------- problem constants ----------------
#define NN   50000
#define EE_  400000
#define EEX  450000   // edges + self loops
#define GG   64
#define DMAX 512
#define HMAX 20
#define EPS_BN 1e-5f
#define NEG_SLOPE 0.2f

// ---------------- static scratch ----------------
__device__ float d_h  [(size_t)NN * DMAX];
__device__ float d_agg[(size_t)NN * DMAX];
__device__ float d_lin[(size_t)NN * 64];
__device__ float d_ssrc[(size_t)NN * HMAX];
__device__ float d_sdst[(size_t)NN * HMAX];
__device__ float d_alpha[(size_t)EEX * HMAX];
__device__ int   d_deg[NN];
__device__ int   d_off[NN + 1];
__device__ int   d_cursor[NN];
__device__ int   d_csr[EEX];
__device__ int   d_partial[128];
__device__ float d_bnsum[DMAX];
__device__ float d_bnsq [DMAX];
__device__ float d_scale[DMAX];
__device__ float d_shift[DMAX];
__device__ float d_pool[GG * 384];
__device__ int   d_cnt [GG];
__device__ float d_pooled[GG * 384];

// ---------------- small utility kernels ----------------
__global__ void zero_f_kernel(float* p, size_t n) {
    size_t t = (size_t)blockIdx.x * blockDim.x + threadIdx.x;
    size_t stride = (size_t)gridDim.x * blockDim.x;
    for (; t < n; t += stride) p[t] = 0.f;
}
__global__ void zero_i_kernel(int* p, int n) {
    int t = blockIdx.x * blockDim.x + threadIdx.x;
    if (t < n) p[t] = 0;
}

// ---------------- CSR build ----------------
__global__ void edge_hist_kernel(const int* __restrict__ ei, int E, int n, int* deg) {
    int t = blockIdx.x * blockDim.x + threadIdx.x;
    int total = E + n;
    if (t >= total) return;
    int dst = (t < E) ? ei[E + t] : (t - E);
    atomicAdd(&deg[dst], 1);
}

__global__ void scan_block_kernel(const int* __restrict__ deg, int* off, int* partial, int n) {
    __shared__ int sm[1024];
    int gid = blockIdx.x * 1024 + threadIdx.x;
    int v = (gid < n) ? deg[gid] : 0;
    sm[threadIdx.x] = v;
    __syncthreads();
    for (int d = 1; d < 1024; d <<= 1) {
        int t = (threadIdx.x >= d) ? sm[threadIdx.x - d] : 0;
        __syncthreads();
        sm[threadIdx.x] += t;
        __syncthreads();
    }
    if (gid < n) off[gid] = sm[threadIdx.x] - v;   // exclusive scan
    if (threadIdx.x == 1023) partial[blockIdx.x] = sm[1023];
}

__global__ void scan_partials_kernel(int* partial, int nb) {
    if (threadIdx.x == 0 && blockIdx.x == 0) {
        int acc = 0;
        for (int i = 0; i < nb; i++) { int t = partial[i]; partial[i] = acc; acc += t; }
    }
}

__global__ void scan_add_kernel(int* off, const int* __restrict__ partial, int* cursor,
                                int n, int total) {
    int gid = blockIdx.x * blockDim.x + threadIdx.x;
    if (gid < n) {
        int v = off[gid] + partial[gid / 1024];
        off[gid] = v;
        cursor[gid] = v;
    }
    if (gid == 0) off[n] = total;
}

__global__ void edge_scatter_kernel(const int* __restrict__ ei, int E, int n,
                                    int* cursor, int* csr_src) {
    int t = blockIdx.x * blockDim.x + threadIdx.x;
    int total = E + n;
    if (t >= total) return;
    int src, dst;
    if (t < E) { src = ei[t]; dst = ei[E + t]; }
    else       { src = t - E; dst = t - E; }
    int pos = atomicAdd(&cursor[dst], 1);
    csr_src[pos] = src;
}

// ---------------- GEMM: C[M,Nd] = A[M,K] @ B[K,Nd] (+bias) ----------------
#define TM 64
#define TN 64
#define TK 16
__global__ void gemm_kernel(const float* __restrict__ A, const float* __restrict__ B,
                            const float* __restrict__ bias, float* __restrict__ C,
                            int M, int K, int Nd) {
    __shared__ float As[TK][TM + 1];
    __shared__ float Bs[TK][TN + 1];
    int tx = threadIdx.x % 16;
    int ty = threadIdx.x / 16;
    int row0 = blockIdx.y * TM;
    int col0 = blockIdx.x * TN;
    float acc[4][4] = {};
    for (int k0 = 0; k0 < K; k0 += TK) {
        #pragma unroll
        for (int i = 0; i < 4; i++) {
            int lin = threadIdx.x + 256 * i;
            int r = lin / TK, c = lin % TK;
            int gr = row0 + r;
            float v = 0.f;
            if (gr < M) v = A[(size_t)gr * K + k0 + c];
            As[c][r] = v;
        }
        #pragma unroll
        for (int i = 0; i < 4; i++) {
            int lin = threadIdx.x + 256 * i;
            int r = lin / TN, c = lin % TN;
            int gc = col0 + c;
            float v = 0.f;
            if (gc < Nd && (k0 + r) < K) v = B[(size_t)(k0 + r) * Nd + gc];
            Bs[r][c] = v;
        }
        __syncthreads();
        #pragma unroll
        for (int kk = 0; kk < TK; kk++) {
            float a[4], b[4];
            #pragma unroll
            for (int i = 0; i < 4; i++) a[i] = As[kk][ty * 4 + i];
            #pragma unroll
            for (int j = 0; j < 4; j++) b[j] = Bs[kk][tx * 4 + j];
            #pragma unroll
            for (int i = 0; i < 4; i++)
                #pragma unroll
                for (int j = 0; j < 4; j++)
                    acc[i][j] += a[i] * b[j];
        }
        __syncthreads();
    }
    #pragma unroll
    for (int i = 0; i < 4; i++) {
        int gr = row0 + ty * 4 + i;
        if (gr >= M) continue;
        #pragma unroll
        for (int j = 0; j < 4; j++) {
            int gc = col0 + tx * 4 + j;
            if (gc >= Nd) continue;
            float v = acc[i][j];
            if (bias) v += bias[gc];
            C[(size_t)gr * Nd + gc] = v;
        }
    }
}

// ---------------- attention scores s_src, s_dst ----------------
__global__ void scores_kernel(const float* __restrict__ h, const float* __restrict__ a_s,
                              const float* __restrict__ a_d, float* ssrc, float* sdst,
                              int M, int H, int C) {
    int t = blockIdx.x * blockDim.x + threadIdx.x;
    if (t >= M * H) return;
    int n = t / H, hh = t % H;
    const float* hr = h + (size_t)n * H * C + hh * C;
    const float* as = a_s + hh * C;
    const float* ad = a_d + hh * C;
    float s1 = 0.f, s2 = 0.f;
    for (int c = 0; c < C; c++) { float v = hr[c]; s1 += v * as[c]; s2 += v * ad[c]; }
    ssrc[t] = s1; sdst[t] = s2;
}

// ---------------- GAT aggregation: one warp per dst node ----------------
__global__ void gat_aggregate_kernel(const float* __restrict__ h,
                                     const float* __restrict__ ssrc,
                                     const float* __restrict__ sdst,
                                     const int* __restrict__ off,
                                     const int* __restrict__ csr_src,
                                     float* __restrict__ alpha,
                                     const float* __restrict__ bias,
                                     float* __restrict__ out,
                                     int M, int H, int C) {
    int warp = (blockIdx.x * blockDim.x + threadIdx.x) >> 5;
    int lane = threadIdx.x & 31;
    if (warp >= M) return;
    int i = warp;
    int beg = off[i], end = off[i + 1];
    int HC = H * C;

    if (lane < H) {
        float sd = sdst[(size_t)i * H + lane];
        float mx = -INFINITY;
        for (int p = beg; p < end; p++) {
            int s = csr_src[p];
            float v = ssrc[(size_t)s * H + lane] + sd;
            v = (v > 0.f) ? v : NEG_SLOPE * v;
            mx = fmaxf(mx, v);
        }
        float z = 0.f;
        for (int p = beg; p < end; p++) {
            int s = csr_src[p];
            float v = ssrc[(size_t)s * H + lane] + sd;
            v = (v > 0.f) ? v : NEG_SLOPE * v;
            float ev = expf(v - mx);
            alpha[(size_t)p * H + lane] = ev;
            z += ev;
        }
        float zinv = 1.f / (z + 1e-16f);
        for (int p = beg; p < end; p++) alpha[(size_t)p * H + lane] *= zinv;
    }
    __syncwarp();

    // phase 3: weighted accumulate. HC is a multiple of 32 (320/512/384).
    int nacc = HC >> 5;
    float acc[16];
    int hidx[16];
    #pragma unroll
    for (int j = 0; j < 16; j++) acc[j] = 0.f;
    for (int j = 0; j < nacc; j++) hidx[j] = (lane + 32 * j) / C;

    for (int p = beg; p < end; p++) {
        int s = csr_src[p];
        const float* hrow = h + (size_t)s * HC;
        const float* arow = alpha + (size_t)p * H;
        for (int j = 0; j < nacc; j++) {
            acc[j] += arow[hidx[j]] * hrow[lane + 32 * j];
        }
    }
    float* orow = out + (size_t)i * HC;
    for (int j = 0; j < nacc; j++) {
        int idx = lane + 32 * j;
        orow[idx] = acc[j] + bias[idx];
    }
}

// ---------------- BatchNorm ----------------
__global__ void bn_stats_kernel(const float* __restrict__ X, int M, int D,
                                float* sum, float* sq) {
    int f = blockIdx.y * blockDim.x + threadIdx.x;
    if (f >= D) return;
    int r0 = blockIdx.x * 256;
    int rend = min(r0 + 256, M);
    float s = 0.f, s2 = 0.f;
    for (int r = r0; r < rend; r++) {
        float v = X[(size_t)r * D + f];
        s += v; s2 += v * v;
    }
    atomicAdd(&sum[f], s);
    atomicAdd(&sq[f], s2);
}

__global__ void bn_finalize_kernel(const float* sum, const float* sq,
                                   const float* __restrict__ g, const float* __restrict__ be,
                                   float* scale, float* shift, int M, int D) {
    int f = blockIdx.x * blockDim.x + threadIdx.x;
    if (f >= D) return;
    float inv = 1.f / (float)M;
    float mu = sum[f] * inv;
    float var = sq[f] * inv - mu * mu;
    float sc = g[f] * rsqrtf(var + EPS_BN);
    scale[f] = sc;
    shift[f] = be[f] - mu * sc;
}

__global__ void bn_apply_relu_kernel(float* __restrict__ X, const float* __restrict__ scale,
                                     const float* __restrict__ shift, int M, int D) {
    size_t t = (size_t)blockIdx.x * blockDim.x + threadIdx.x;
    size_t total = (size_t)M * D;
    size_t stride = (size_t)gridDim.x * blockDim.x;
    for (; t < total; t += stride) {
        int f = (int)(t % (size_t)D);
        float v = X[t] * scale[f] + shift[f];
        X[t] = fmaxf(v, 0.f);
    }
}

// ---------------- pooling ----------------
__global__ void pool_kernel(const float* __restrict__ h, const int* __restrict__ batch,
                            float* pool, int M, int D) {
    size_t t = (size_t)blockIdx.x * blockDim.x + threadIdx.x;
    size_t total = (size_t)M * D;
    size_t stride = (size_t)gridDim.x * blockDim.x;
    for (; t < total; t += stride) {
        int n = (int)(t / D);
        int f = (int)(t % (size_t)D);
        atomicAdd(&pool[batch[n] * D + f], h[t]);
    }
}
__global__ void cnt_kernel(const int* __restrict__ batch, int* cnt, int M) {
    int t = blockIdx.x * blockDim.x + threadIdx.x;
    if (t < M) atomicAdd(&cnt[batch[t]], 1);
}
__global__ void pool_div_kernel(float* pooled, const float* pool, const int* cnt, int G, int D) {
    int t = blockIdx.x * blockDim.x + threadIdx.x;
    if (t >= G * D) return;
    int g = t / D;
    float c = fmaxf((float)cnt[g], 1.f);
    pooled[t] = pool[t] / c;
}

// ---------------- host-side orchestration ----------------
static void launch_gemm(const float* A, const float* B, const float* bias, float* C,
                        int M, int K, int Nd) {
    dim3 grid((Nd + TN - 1) / TN, (M + TM - 1) / TM);
    gemm_kernel<<<grid, 256>>>(A, B, bias, C, M, K, Nd);
}

struct Ptrs {
    float *h, *agg, *lin, *ssrc, *sdst, *alpha;
    int *deg, *off, *cursor, *csr, *partial;
    float *bnsum, *bnsq, *scale, *shift, *pool, *pooled;
    int *cnt;
};

static void run_bn_relu(float* X, int M, int D, const float* g, const float* be, Ptrs& P) {
    zero_f_kernel<<<2, 256>>>(P.bnsum, D);
    zero_f_kernel<<<2, 256>>>(P.bnsq, D);
    dim3 sg((M + 255) / 256, (D + 255) / 256);
    bn_stats_kernel<<<sg, 256>>>(X, M, D, P.bnsum, P.bnsq);
    bn_finalize_kernel<<<(D + 255) / 256, 256>>>(P.bnsum, P.bnsq, g, be, P.scale, P.shift, M, D);
    size_t total = (size_t)M * D;
    int blocks = (int)min((total + 255) / 256, (size_t)4096);
    bn_apply_relu_kernel<<<blocks, 256>>>(X, P.scale, P.shift, M, D);
}

static void run_gat_layer(const float* X, int din, const float* W,
                          const float* a_s, const float* a_d, const float* bias,
                          int H, int C, int M, Ptrs& P) {
    int HC = H * C;
    launch_gemm(X, W, nullptr, P.h, M, din, HC);
    scores_kernel<<<(M * H + 255) / 256, 256>>>(P.h, a_s, a_d, P.ssrc, P.sdst, M, H, C);
    int warps_per_block = 8;
    int blocks = (M + warps_per_block - 1) / warps_per_block;
    gat_aggregate_kernel<<<blocks, warps_per_block * 32>>>(
        P.h, P.ssrc, P.sdst, P.off, P.csr, P.alpha, bias, P.agg, M, H, C);
}

extern "C" void kernel_launch(void* const* d_in, const int* in_sizes, int n_in,
                              void* d_out, int out_size) {
    const float* x     = (const float*)d_in[0];
    const int*   ei    = (const int*)  d_in[1];
    const int*   batch = (const int*)  d_in[2];
    const float* W1  = (const float*)d_in[3];
    const float* as1 = (const float*)d_in[4];
    const float* ad1 = (const float*)d_in[5];
    const float* b1  = (const float*)d_in[6];
    const float* g1  = (const float*)d_in[7];
    const float* be1 = (const float*)d_in[8];
    const float* lw1 = (const float*)d_in[9];
    const float* lb1 = (const float*)d_in[10];
    const float* gl1 = (const float*)d_in[11];
    const float* bel1= (const float*)d_in[12];
    const float* W2  = (const float*)d_in[13];
    const float* as2 = (const float*)d_in[14];
    const float* ad2 = (const float*)d_in[15];
    const float* b2  = (const float*)d_in[16];
    const float* g2  = (const float*)d_in[17];
    const float* be2 = (const float*)d_in[18];
    const float* lw2 = (const float*)d_in[19];
    const float* lb2 = (const float*)d_in[20];
    const float* gl2 = (const float*)d_in[21];
    const float* bel2= (const float*)d_in[22];
    const float* W3  = (const float*)d_in[23];
    const float* as3 = (const float*)d_in[24];
    const float* ad3 = (const float*)d_in[25];
    const float* b3  = (const float*)d_in[26];
    const float* g3  = (const float*)d_in[27];
    const float* be3 = (const float*)d_in[28];
    const float* lwf = (const float*)d_in[29];
    const float* lbf = (const float*)d_in[30];

    int M = in_sizes[2];            // 50000 nodes
    int E = in_sizes[1] / 2;        // 400000 edges
    int EX = E + M;                 // + self loops

    Ptrs P;
    cudaGetSymbolAddress((void**)&P.h, d_h);
    cudaGetSymbolAddress((void**)&P.agg, d_agg);
    cudaGetSymbolAddress((void**)&P.lin, d_lin);
    cudaGetSymbolAddress((void**)&P.ssrc, d_ssrc);
    cudaGetSymbolAddress((void**)&P.sdst, d_sdst);
    cudaGetSymbolAddress((void**)&P.alpha, d_alpha);
    cudaGetSymbolAddress((void**)&P.deg, d_deg);
    cudaGetSymbolAddress((void**)&P.off, d_off);
    cudaGetSymbolAddress((void**)&P.cursor, d_cursor);
    cudaGetSymbolAddress((void**)&P.csr, d_csr);
    cudaGetSymbolAddress((void**)&P.partial, d_partial);
    cudaGetSymbolAddress((void**)&P.bnsum, d_bnsum);
    cudaGetSymbolAddress((void**)&P.bnsq, d_bnsq);
    cudaGetSymbolAddress((void**)&P.scale, d_scale);
    cudaGetSymbolAddress((void**)&P.shift, d_shift);
    cudaGetSymbolAddress((void**)&P.pool, d_pool);
    cudaGetSymbolAddress((void**)&P.pooled, d_pooled);
    cudaGetSymbolAddress((void**)&P.cnt, d_cnt);

    // ---- CSR build (shared by all three GAT layers) ----
    zero_i_kernel<<<(M + 255) / 256, 256>>>(P.deg, M);
    edge_hist_kernel<<<(EX + 255) / 256, 256>>>(ei, E, M, P.deg);
    int nb = (M + 1023) / 1024;
    scan_block_kernel<<<nb, 1024>>>(P.deg, P.off, P.partial, M);
    scan_partials_kernel<<<1, 1>>>(P.partial, nb);
    scan_add_kernel<<<(M + 255) / 256, 256>>>(P.off, P.partial, P.cursor, M, EX);
    edge_scatter_kernel<<<(EX + 255) / 256, 256>>>(ei, E, M, P.cursor, P.csr);

    // ---- Layer 1: GAT(128 -> 20x16=320), BN+ReLU, Linear 320->16, BN+ReLU ----
    run_gat_layer(x, 128, W1, as1, ad1, b1, 20, 16, M, P);
    run_bn_relu(P.agg, M, 320, g1, be1, P);
    launch_gemm(P.agg, lw1, lb1, P.lin, M, 320, 16);
    run_bn_relu(P.lin, M, 16, gl1, bel1, P);

    // ---- Layer 2: GAT(16 -> 16x32=512), BN+ReLU, Linear 512->32, BN+ReLU ----
    run_gat_layer(P.lin, 16, W2, as2, ad2, b2, 16, 32, M, P);
    run_bn_relu(P.agg, M, 512, g2, be2, P);
    launch_gemm(P.agg, lw2, lb2, P.lin, M, 512, 32);
    run_bn_relu(P.lin, M, 512 == 512 ? 32 : 32, gl2, bel2, P);

    // ---- Layer 3: GAT(32 -> 8x48=384), BN+ReLU ----
    run_gat_layer(P.lin, 32, W3, as3, ad3, b3, 8, 48, M, P);
    run_bn_relu(P.agg, M, 384, g3, be3, P);

    // ---- global mean pool + final linear ----
    zero_f_kernel<<<(GG * 384 + 255) / 256, 256>>>(P.pool, GG * 384);
    zero_i_kernel<<<1, GG>>>(P.cnt, GG);
    {
        size_t total = (size_t)M * 384;
        int blocks = (int)min((total + 255) / 256, (size_t)4096);
        pool_kernel<<<blocks, 256>>>(P.agg, batch, P.pool, M, 384);
    }
    cnt_kernel<<<(M + 255) / 256, 256>>>(batch, P.cnt, M);
    pool_div_kernel<<<(GG * 384 + 255) / 256, 256>>>(P.pooled, P.pool, P.cnt, GG, 384);
    launch_gemm(P.pooled, lwf, lbf, (float*)d_out, GG, 384, 10);
}

// round 2
// speedup vs baseline: 1.3502x; 1.3502x over previous
#include <cuda_runtime.h>
#include <cuda_bf16.h>
#include <math.h>

// ---------------- problem constants ----------------
#define NN   50000
#define EEX  450000   // edges + self loops
#define GG   64
#define DMAX 512
#define HMAX 20
#define EPS_BN 1e-5f
#define NEG_SLOPE 0.2f

// ---------------- static scratch ----------------
__device__ float d_h  [(size_t)NN * DMAX];
__device__ float d_agg[(size_t)NN * DMAX];
__device__ float d_lin[(size_t)NN * 64];
__device__ float d_ssrc[(size_t)NN * HMAX];
__device__ float d_sdst[(size_t)NN * HMAX];
__device__ int   d_deg[NN];
__device__ int   d_off[NN + 1];
__device__ int   d_cursor[NN];
__device__ int   d_csr[EEX];
__device__ int   d_partial[128];
__device__ float d_bnsum[DMAX];
__device__ float d_bnsq [DMAX];
__device__ float d_scale[DMAX];
__device__ float d_shift[DMAX];
__device__ float d_pool[GG * 384];
__device__ int   d_cnt [GG];
__device__ float d_pooled[GG * 384];

// ---------------- small utility kernels ----------------
__global__ void zero_f_kernel(float* p, size_t n) {
    size_t t = (size_t)blockIdx.x * blockDim.x + threadIdx.x;
    size_t stride = (size_t)gridDim.x * blockDim.x;
    for (; t < n; t += stride) p[t] = 0.f;
}
__global__ void zero_i_kernel(int* p, int n) {
    int t = blockIdx.x * blockDim.x + threadIdx.x;
    if (t < n) p[t] = 0;
}

// ---------------- CSR build ----------------
__global__ void edge_hist_kernel(const int* __restrict__ ei, int E, int n, int* deg) {
    int t = blockIdx.x * blockDim.x + threadIdx.x;
    int total = E + n;
    if (t >= total) return;
    int dst = (t < E) ? ei[E + t] : (t - E);
    atomicAdd(&deg[dst], 1);
}

__global__ void scan_block_kernel(const int* __restrict__ deg, int* off, int* partial, int n) {
    __shared__ int sm[1024];
    int gid = blockIdx.x * 1024 + threadIdx.x;
    int v = (gid < n) ? deg[gid] : 0;
    sm[threadIdx.x] = v;
    __syncthreads();
    for (int d = 1; d < 1024; d <<= 1) {
        int t = (threadIdx.x >= d) ? sm[threadIdx.x - d] : 0;
        __syncthreads();
        sm[threadIdx.x] += t;
        __syncthreads();
    }
    if (gid < n) off[gid] = sm[threadIdx.x] - v;   // exclusive scan
    if (threadIdx.x == 1023) partial[blockIdx.x] = sm[1023];
}

__global__ void scan_partials_kernel(int* partial, int nb) {
    if (threadIdx.x == 0 && blockIdx.x == 0) {
        int acc = 0;
        for (int i = 0; i < nb; i++) { int t = partial[i]; partial[i] = acc; acc += t; }
    }
}

__global__ void scan_add_kernel(int* off, const int* __restrict__ partial, int* cursor,
                                int n, int total) {
    int gid = blockIdx.x * blockDim.x + threadIdx.x;
    if (gid < n) {
        int v = off[gid] + partial[gid / 1024];
        off[gid] = v;
        cursor[gid] = v;
    }
    if (gid == 0) off[n] = total;
}

__global__ void edge_scatter_kernel(const int* __restrict__ ei, int E, int n,
                                    int* cursor, int* csr_src) {
    int t = blockIdx.x * blockDim.x + threadIdx.x;
    int total = E + n;
    if (t >= total) return;
    int src, dst;
    if (t < E) { src = ei[t]; dst = ei[E + t]; }
    else       { src = t - E; dst = t - E; }
    int pos = atomicAdd(&cursor[dst], 1);
    csr_src[pos] = src;
}

// ---------------- tensor-core GEMM (3xTF32 for fp32 accuracy) ----------------
// C[M,N] = op(A)[M,K] @ B[K,N] (+bias), where op(A) = relu(A*tscale + tshift)
// per K-column if tscale != null (fused BatchNorm+ReLU on the input).
#define GBM 128
#define GBN 64
#define GBK 16

__device__ __forceinline__ void split_tf32(float x, unsigned& hi, unsigned& lo) {
    unsigned h_;
    asm("cvt.rna.tf32.f32 %0, %1;" : "=r"(h_) : "f"(x));
    float lf = x - __uint_as_float(h_);
    unsigned l_;
    asm("cvt.rna.tf32.f32 %0, %1;" : "=r"(l_) : "f"(lf));
    hi = h_; lo = l_;
}

__device__ __forceinline__ void mma_tf32(float c[4], const unsigned a[4], const unsigned b[2]) {
    asm volatile(
        "mma.sync.aligned.m16n8k8.row.col.f32.tf32.tf32.f32 "
        "{%0,%1,%2,%3}, {%4,%5,%6,%7}, {%8,%9}, {%0,%1,%2,%3};"
        : "+f"(c[0]), "+f"(c[1]), "+f"(c[2]), "+f"(c[3])
        : "r"(a[0]), "r"(a[1]), "r"(a[2]), "r"(a[3]), "r"(b[0]), "r"(b[1]));
}

__global__ __launch_bounds__(256) void gemm_tc_kernel(
    const float* __restrict__ A, const float* __restrict__ B,
    const float* __restrict__ bias,
    const float* __restrict__ tscale, const float* __restrict__ tshift,
    float* __restrict__ C_, int M, int K, int N)
{
    __shared__ float As[GBK][GBM + 4];
    __shared__ float Bs[GBK][GBN + 4];
    int tid = threadIdx.x;
    int warp = tid >> 5, lane = tid & 31;
    int wm = warp & 3, wn = warp >> 2;   // warp tile (wm*32, wn*32)
    int row0 = blockIdx.y * GBM;
    int col0 = blockIdx.x * GBN;
    int g = lane >> 2, t4 = lane & 3;

    float c[2][4][4];
    #pragma unroll
    for (int mm = 0; mm < 2; mm++)
        #pragma unroll
        for (int nn = 0; nn < 4; nn++)
            #pragma unroll
            for (int q = 0; q < 4; q++) c[mm][nn][q] = 0.f;

    for (int k0 = 0; k0 < K; k0 += GBK) {
        // A tile: 128x16 floats, float4 loads, 2 per thread, stored transposed.
        #pragma unroll
        for (int i = 0; i < 2; i++) {
            int idx = tid + 256 * i;           // 0..511 float4s
            int r = idx >> 2, c4 = idx & 3;
            int gr = row0 + r;
            float4 v = make_float4(0.f, 0.f, 0.f, 0.f);
            if (gr < M) v = *(const float4*)&A[(size_t)gr * K + k0 + c4 * 4];
            if (tscale) {
                int kb = k0 + c4 * 4;
                v.x = fmaxf(v.x * tscale[kb+0] + tshift[kb+0], 0.f);
                v.y = fmaxf(v.y * tscale[kb+1] + tshift[kb+1], 0.f);
                v.z = fmaxf(v.z * tscale[kb+2] + tshift[kb+2], 0.f);
                v.w = fmaxf(v.w * tscale[kb+3] + tshift[kb+3], 0.f);
            }
            As[c4*4+0][r] = v.x; As[c4*4+1][r] = v.y;
            As[c4*4+2][r] = v.z; As[c4*4+3][r] = v.w;
        }
        // B tile: 16x64 floats, scalar guarded loads, 4 per thread.
        #pragma unroll
        for (int i = 0; i < 4; i++) {
            int idx = tid + 256 * i;           // 0..1023
            int r = idx >> 6, cc = idx & 63;
            int gc = col0 + cc;
            float v = 0.f;
            if (gc < N) v = B[(size_t)(k0 + r) * N + gc];
            Bs[r][cc] = v;
        }
        __syncthreads();

        #pragma unroll
        for (int ks = 0; ks < GBK; ks += 8) {
            unsigned ahi[2][4], alo[2][4], bhi[4][2], blo[4][2];
            #pragma unroll
            for (int mm = 0; mm < 2; mm++) {
                int mrow = wm * 32 + mm * 16 + g;
                split_tf32(As[ks + t4][mrow],        ahi[mm][0], alo[mm][0]);
                split_tf32(As[ks + t4][mrow + 8],    ahi[mm][1], alo[mm][1]);
                split_tf32(As[ks + t4 + 4][mrow],    ahi[mm][2], alo[mm][2]);
                split_tf32(As[ks + t4 + 4][mrow + 8],ahi[mm][3], alo[mm][3]);
            }
            #pragma unroll
            for (int nn = 0; nn < 4; nn++) {
                int ncol = wn * 32 + nn * 8 + g;
                split_tf32(Bs[ks + t4][ncol],     bhi[nn][0], blo[nn][0]);
                split_tf32(Bs[ks + t4 + 4][ncol], bhi[nn][1], blo[nn][1]);
            }
            #pragma unroll
            for (int mm = 0; mm < 2; mm++)
                #pragma unroll
                for (int nn = 0; nn < 4; nn++) {
                    mma_tf32(c[mm][nn], ahi[mm], bhi[nn]);
                    mma_tf32(c[mm][nn], alo[mm], bhi[nn]);
                    mma_tf32(c[mm][nn], ahi[mm], blo[nn]);
                }
        }
        __syncthreads();
    }

    #pragma unroll
    for (int mm = 0; mm < 2; mm++) {
        int rbase = row0 + wm * 32 + mm * 16 + g;
        #pragma unroll
        for (int nn = 0; nn < 4; nn++) {
            int cbase = col0 + wn * 32 + nn * 8 + t4 * 2;
            #pragma unroll
            for (int q = 0; q < 4; q++) {
                int rr = rbase + ((q >= 2) ? 8 : 0);
                int cc = cbase + (q & 1);
                if (rr < M && cc < N) {
                    float v = c[mm][nn][q];
                    if (bias) v += bias[cc];
                    C_[(size_t)rr * N + cc] = v;
                }
            }
        }
    }
}

// ---------------- attention scores s_src, s_dst ----------------
__global__ void scores_kernel(const float* __restrict__ h, const float* __restrict__ a_s,
                              const float* __restrict__ a_d, float* ssrc, float* sdst,
                              int M, int H, int C) {
    int t = blockIdx.x * blockDim.x + threadIdx.x;
    if (t >= M * H) return;
    int n = t / H, hh = t % H;
    const float* hr = h + (size_t)n * H * C + hh * C;
    const float* as = a_s + hh * C;
    const float* ad = a_d + hh * C;
    float s1 = 0.f, s2 = 0.f;
    for (int cc = 0; cc < C; cc++) { float v = hr[cc]; s1 += v * as[cc]; s2 += v * ad[cc]; }
    ssrc[t] = s1; sdst[t] = s2;
}

// ---------------- GAT aggregation: one warp per dst node, no alpha array ----
template <int H, int C>
__global__ void gat_aggregate_kernel(const float* __restrict__ h,
                                     const float* __restrict__ ssrc,
                                     const float* __restrict__ sdst,
                                     const int* __restrict__ off,
                                     const int* __restrict__ csr_src,
                                     const float* __restrict__ bias,
                                     float* __restrict__ out, int M) {
    constexpr int HC = H * C;
    constexpr int N2 = HC / 64;   // float2 per lane
    int warp = (blockIdx.x * blockDim.x + threadIdx.x) >> 5;
    int lane = threadIdx.x & 31;
    if (warp >= M) return;
    int i = warp;
    int beg = off[i], end = off[i + 1];

    float sd = 0.f, mx = -INFINITY;
    if (lane < H) sd = sdst[(size_t)i * H + lane];
    for (int p = beg; p < end; p++) {
        int s = __ldg(&csr_src[p]);
        if (lane < H) {
            float v = ssrc[(size_t)s * H + lane] + sd;
            v = (v > 0.f) ? v : NEG_SLOPE * v;
            mx = fmaxf(mx, v);
        }
    }

    float z = 0.f;
    float2 acc[N2];
    int hd[N2];
    #pragma unroll
    for (int j = 0; j < N2; j++) {
        acc[j] = make_float2(0.f, 0.f);
        hd[j] = (2 * (lane + 32 * j)) / C;
    }
    for (int p = beg; p < end; p++) {
        int s = __ldg(&csr_src[p]);
        float ev = 0.f;
        if (lane < H) {
            float v = ssrc[(size_t)s * H + lane] + sd;
            v = (v > 0.f) ? v : NEG_SLOPE * v;
            ev = __expf(v - mx);
            z += ev;
        }
        const float2* hrow = (const float2*)(h + (size_t)s * HC);
        #pragma unroll
        for (int j = 0; j < N2; j++) {
            float a = __shfl_sync(0xffffffffu, ev, hd[j]);
            float2 hv = __ldg(&hrow[lane + 32 * j]);
            acc[j].x += a * hv.x;
            acc[j].y += a * hv.y;
        }
    }
    float zinv = (lane < H) ? 1.f / (z + 1e-16f) : 0.f;
    const float2* b2 = (const float2*)bias;
    float2* o2 = (float2*)(out + (size_t)i * HC);
    #pragma unroll
    for (int j = 0; j < N2; j++) {
        float zi = __shfl_sync(0xffffffffu, zinv, hd[j]);
        int idx = lane + 32 * j;
        float2 bb = b2[idx];
        o2[idx] = make_float2(acc[j].x * zi + bb.x, acc[j].y * zi + bb.y);
    }
}

// ---------------- BatchNorm (stats only; apply is fused into consumers) ----
__global__ void bn_stats_kernel(const float* __restrict__ X, int M, int D,
                                float* sum, float* sq) {
    int f = blockIdx.y * blockDim.x + threadIdx.x;
    if (f >= D) return;
    int r0 = blockIdx.x * 256;
    int rend = min(r0 + 256, M);
    float s = 0.f, s2 = 0.f;
    for (int r = r0; r < rend; r++) {
        float v = X[(size_t)r * D + f];
        s += v; s2 += v * v;
    }
    atomicAdd(&sum[f], s);
    atomicAdd(&sq[f], s2);
}

__global__ void bn_finalize_kernel(const float* sum, const float* sq,
                                   const float* __restrict__ g, const float* __restrict__ be,
                                   float* scale, float* shift, int M, int D) {
    int f = blockIdx.x * blockDim.x + threadIdx.x;
    if (f >= D) return;
    float inv = 1.f / (float)M;
    float mu = sum[f] * inv;
    float var = sq[f] * inv - mu * mu;
    float sc = g[f] * rsqrtf(var + EPS_BN);
    scale[f] = sc;
    shift[f] = be[f] - mu * sc;
}

// ---------------- pooling (fused BN3 apply + ReLU) ----------------
__global__ void pool_bn_kernel(const float* __restrict__ h, const int* __restrict__ batch,
                               const float* __restrict__ scale, const float* __restrict__ shift,
                               float* pool, int M, int D) {
    size_t t = (size_t)blockIdx.x * blockDim.x + threadIdx.x;
    size_t total = (size_t)M * D;
    size_t stride = (size_t)gridDim.x * blockDim.x;
    for (; t < total; t += stride) {
        int n = (int)(t / D);
        int f = (int)(t % (size_t)D);
        float v = fmaxf(h[t] * scale[f] + shift[f], 0.f);
        atomicAdd(&pool[batch[n] * D + f], v);
    }
}
__global__ void cnt_kernel(const int* __restrict__ batch, int* cnt, int M) {
    int t = blockIdx.x * blockDim.x + threadIdx.x;
    if (t < M) atomicAdd(&cnt[batch[t]], 1);
}
__global__ void pool_div_kernel(float* pooled, const float* pool, const int* cnt, int G, int D) {
    int t = blockIdx.x * blockDim.x + threadIdx.x;
    if (t >= G * D) return;
    int g = t / D;
    float c = fmaxf((float)cnt[g], 1.f);
    pooled[t] = pool[t] / c;
}

// ---------------- host-side orchestration ----------------
struct Ptrs {
    float *h, *agg, *lin, *ssrc, *sdst;
    int *deg, *off, *cursor, *csr, *partial;
    float *bnsum, *bnsq, *scale, *shift, *pool, *pooled;
    int *cnt;
};

static void launch_gemm(const float* A, const float* B, const float* bias,
                        const float* tscale, const float* tshift, float* C,
                        int M, int K, int N) {
    dim3 grid((N + GBN - 1) / GBN, (M + GBM - 1) / GBM);
    gemm_tc_kernel<<<grid, 256>>>(A, B, bias, tscale, tshift, C, M, K, N);
}

static void run_bn_stats(const float* X, int M, int D, const float* g, const float* be, Ptrs& P) {
    zero_f_kernel<<<2, 256>>>(P.bnsum, D);
    zero_f_kernel<<<2, 256>>>(P.bnsq, D);
    dim3 sg((M + 255) / 256, (D + 255) / 256);
    bn_stats_kernel<<<sg, 256>>>(X, M, D, P.bnsum, P.bnsq);
    bn_finalize_kernel<<<(D + 255) / 256, 256>>>(P.bnsum, P.bnsq, g, be, P.scale, P.shift, M, D);
}

extern "C" void kernel_launch(void* const* d_in, const int* in_sizes, int n_in,
                              void* d_out, int out_size) {
    const float* x     = (const float*)d_in[0];
    const int*   ei    = (const int*)  d_in[1];
    const int*   batch = (const int*)  d_in[2];
    const float* W1  = (const float*)d_in[3];
    const float* as1 = (const float*)d_in[4];
    const float* ad1 = (const float*)d_in[5];
    const float* b1  = (const float*)d_in[6];
    const float* g1  = (const float*)d_in[7];
    const float* be1 = (const float*)d_in[8];
    const float* lw1 = (const float*)d_in[9];
    const float* lb1 = (const float*)d_in[10];
    const float* gl1 = (const float*)d_in[11];
    const float* bel1= (const float*)d_in[12];
    const float* W2  = (const float*)d_in[13];
    const float* as2 = (const float*)d_in[14];
    const float* ad2 = (const float*)d_in[15];
    const float* b2  = (const float*)d_in[16];
    const float* g2  = (const float*)d_in[17];
    const float* be2 = (const float*)d_in[18];
    const float* lw2 = (const float*)d_in[19];
    const float* lb2 = (const float*)d_in[20];
    const float* gl2 = (const float*)d_in[21];
    const float* bel2= (const float*)d_in[22];
    const float* W3  = (const float*)d_in[23];
    const float* as3 = (const float*)d_in[24];
    const float* ad3 = (const float*)d_in[25];
    const float* b3  = (const float*)d_in[26];
    const float* g3  = (const float*)d_in[27];
    const float* be3 = (const float*)d_in[28];
    const float* lwf = (const float*)d_in[29];
    const float* lbf = (const float*)d_in[30];

    int M = in_sizes[2];            // 50000 nodes
    int E = in_sizes[1] / 2;        // 400000 edges
    int EX = E + M;

    Ptrs P;
    cudaGetSymbolAddress((void**)&P.h, d_h);
    cudaGetSymbolAddress((void**)&P.agg, d_agg);
    cudaGetSymbolAddress((void**)&P.lin, d_lin);
    cudaGetSymbolAddress((void**)&P.ssrc, d_ssrc);
    cudaGetSymbolAddress((void**)&P.sdst, d_sdst);
    cudaGetSymbolAddress((void**)&P.deg, d_deg);
    cudaGetSymbolAddress((void**)&P.off, d_off);
    cudaGetSymbolAddress((void**)&P.cursor, d_cursor);
    cudaGetSymbolAddress((void**)&P.csr, d_csr);
    cudaGetSymbolAddress((void**)&P.partial, d_partial);
    cudaGetSymbolAddress((void**)&P.bnsum, d_bnsum);
    cudaGetSymbolAddress((void**)&P.bnsq, d_bnsq);
    cudaGetSymbolAddress((void**)&P.scale, d_scale);
    cudaGetSymbolAddress((void**)&P.shift, d_shift);
    cudaGetSymbolAddress((void**)&P.pool, d_pool);
    cudaGetSymbolAddress((void**)&P.pooled, d_pooled);
    cudaGetSymbolAddress((void**)&P.cnt, d_cnt);

    // ---- CSR build (shared by all three GAT layers) ----
    zero_i_kernel<<<(M + 255) / 256, 256>>>(P.deg, M);
    edge_hist_kernel<<<(EX + 255) / 256, 256>>>(ei, E, M, P.deg);
    int nb = (M + 1023) / 1024;
    scan_block_kernel<<<nb, 1024>>>(P.deg, P.off, P.partial, M);
    scan_partials_kernel<<<1, 1>>>(P.partial, nb);
    scan_add_kernel<<<(M + 255) / 256, 256>>>(P.off, P.partial, P.cursor, M, EX);
    edge_scatter_kernel<<<(EX + 255) / 256, 256>>>(ei, E, M, P.cursor, P.csr);

    int wpb = 8, ablk;

    // ---- Layer 1: GAT(128 -> 20x16=320) ----
    launch_gemm(x, W1, nullptr, nullptr, nullptr, P.h, M, 128, 320);
    scores_kernel<<<(M * 20 + 255) / 256, 256>>>(P.h, as1, ad1, P.ssrc, P.sdst, M, 20, 16);
    ablk = (M + wpb - 1) / wpb;
    gat_aggregate_kernel<20, 16><<<ablk, wpb * 32>>>(P.h, P.ssrc, P.sdst, P.off, P.csr, b1, P.agg, M);
    run_bn_stats(P.agg, M, 320, g1, be1, P);
    // lin1 with fused BN1+ReLU on input
    launch_gemm(P.agg, lw1, lb1, P.scale, P.shift, P.lin, M, 320, 16);
    run_bn_stats(P.lin, M, 16, gl1, bel1, P);

    // ---- Layer 2: GAT(16 -> 16x32=512) ----
    launch_gemm(P.lin, W2, nullptr, P.scale, P.shift, P.h, M, 16, 512);
    scores_kernel<<<(M * 16 + 255) / 256, 256>>>(P.h, as2, ad2, P.ssrc, P.sdst, M, 16, 32);
    gat_aggregate_kernel<16, 32><<<ablk, wpb * 32>>>(P.h, P.ssrc, P.sdst, P.off, P.csr, b2, P.agg, M);
    run_bn_stats(P.agg, M, 512, g2, be2, P);
    launch_gemm(P.agg, lw2, lb2, P.scale, P.shift, P.lin, M, 512, 32);
    run_bn_stats(P.lin, M, 32, gl2, bel2, P);

    // ---- Layer 3: GAT(32 -> 8x48=384) ----
    launch_gemm(P.lin, W3, nullptr, P.scale, P.shift, P.h, M, 32, 384);
    scores_kernel<<<(M * 8 + 255) / 256, 256>>>(P.h, as3, ad3, P.ssrc, P.sdst, M, 8, 48);
    gat_aggregate_kernel<8, 48><<<ablk, wpb * 32>>>(P.h, P.ssrc, P.sdst, P.off, P.csr, b3, P.agg, M);
    run_bn_stats(P.agg, M, 384, g3, be3, P);

    // ---- global mean pool (fused BN3+ReLU) + final linear ----
    zero_f_kernel<<<(GG * 384 + 255) / 256, 256>>>(P.pool, GG * 384);
    zero_i_kernel<<<1, GG>>>(P.cnt, GG);
    {
        size_t total = (size_t)M * 384;
        int blocks = (int)min((total + 255) / 256, (size_t)4096);
        pool_bn_kernel<<<blocks, 256>>>(P.agg, batch, P.scale, P.shift, P.pool, M, 384);
    }
    cnt_kernel<<<(M + 255) / 256, 256>>>(batch, P.cnt, M);
    pool_div_kernel<<<(GG * 384 + 255) / 256, 256>>>(P.pooled, P.pool, P.cnt, GG, 384);
    launch_gemm(P.pooled, lwf, lbf, nullptr, nullptr, (float*)d_out, GG, 384, 10);
}

// round 3
// speedup vs baseline: 1.3778x; 1.0205x over previous
#include <cuda_runtime.h>
#include <cuda_bf16.h>
#include <math.h>

// ---------------- problem constants ----------------
#define NN   50000
#define EEX  450000   // edges + self loops
#define GG   64
#define DMAX 512
#define HMAX 20
#define EPS_BN 1e-5f
#define NEG_SLOPE 0.2f
#define BN_ROWS 512

// ---------------- static scratch ----------------
__device__ float d_h  [(size_t)NN * DMAX];
__device__ float d_agg[(size_t)NN * DMAX];
__device__ float d_lin[(size_t)NN * 64];
__device__ float d_ssrc[(size_t)NN * HMAX];
__device__ float d_sdst[(size_t)NN * HMAX];
__device__ float d_alpha[(size_t)EEX * HMAX];
__device__ float d_zinv[(size_t)NN * HMAX];
__device__ int   d_deg[NN];
__device__ int   d_off[NN + 1];
__device__ int   d_cursor[NN];
__device__ int   d_csr[EEX];
__device__ int   d_partial[128];
__device__ float d_bnpsum[128 * DMAX];
__device__ float d_bnpsq [128 * DMAX];
__device__ float d_scale[DMAX];
__device__ float d_shift[DMAX];
__device__ float d_pool[GG * 384];
__device__ int   d_cnt [GG];
__device__ float d_pooled[GG * 384];

// ---------------- small utility kernels ----------------
__global__ void zero_i_kernel(int* p, int n) {
    int t = blockIdx.x * blockDim.x + threadIdx.x;
    if (t < n) p[t] = 0;
}
__global__ void zero_pool_kernel(float* pool, int* cnt) {
    int t = blockIdx.x * blockDim.x + threadIdx.x;
    if (t < GG * 384) pool[t] = 0.f;
    if (t < GG) cnt[t] = 0;
}

// ---------------- CSR build ----------------
__global__ void edge_hist_kernel(const int* __restrict__ ei, int E, int n, int* deg) {
    int t = blockIdx.x * blockDim.x + threadIdx.x;
    int total = E + n;
    if (t >= total) return;
    int dst = (t < E) ? ei[E + t] : (t - E);
    atomicAdd(&deg[dst], 1);
}

__global__ void scan_block_kernel(const int* __restrict__ deg, int* off, int* partial, int n) {
    __shared__ int sm[1024];
    int gid = blockIdx.x * 1024 + threadIdx.x;
    int v = (gid < n) ? deg[gid] : 0;
    sm[threadIdx.x] = v;
    __syncthreads();
    for (int d = 1; d < 1024; d <<= 1) {
        int t = (threadIdx.x >= d) ? sm[threadIdx.x - d] : 0;
        __syncthreads();
        sm[threadIdx.x] += t;
        __syncthreads();
    }
    if (gid < n) off[gid] = sm[threadIdx.x] - v;   // exclusive within block
    if (threadIdx.x == 1023) partial[blockIdx.x] = sm[1023];
}

__global__ void scan_add_kernel(int* off, const int* __restrict__ partial, int* cursor,
                                int n, int total) {
    int gid = blockIdx.x * blockDim.x + threadIdx.x;
    if (gid < n) {
        int pb = gid >> 10;
        int base = 0;
        for (int j = 0; j < pb; j++) base += partial[j];
        int v = off[gid] + base;
        off[gid] = v;
        cursor[gid] = v;
    }
    if (gid == 0) off[n] = total;
}

__global__ void edge_scatter_kernel(const int* __restrict__ ei, int E, int n,
                                    int* cursor, int* csr_src) {
    int t = blockIdx.x * blockDim.x + threadIdx.x;
    int total = E + n;
    if (t >= total) return;
    int src, dst;
    if (t < E) { src = ei[t]; dst = ei[E + t]; }
    else       { src = t - E; dst = t - E; }
    int pos = atomicAdd(&cursor[dst], 1);
    csr_src[pos] = src;
}

// ---------------- tensor-core GEMM (3xTF32 for fp32 accuracy) ----------------
#define GBM 128
#define GBN 64
#define GBK 16

__device__ __forceinline__ void split_tf32(float x, unsigned& hi, unsigned& lo) {
    unsigned h_;
    asm("cvt.rna.tf32.f32 %0, %1;" : "=r"(h_) : "f"(x));
    float lf = x - __uint_as_float(h_);
    unsigned l_;
    asm("cvt.rna.tf32.f32 %0, %1;" : "=r"(l_) : "f"(lf));
    hi = h_; lo = l_;
}

__device__ __forceinline__ void mma_tf32(float c[4], const unsigned a[4], const unsigned b[2]) {
    asm volatile(
        "mma.sync.aligned.m16n8k8.row.col.f32.tf32.tf32.f32 "
        "{%0,%1,%2,%3}, {%4,%5,%6,%7}, {%8,%9}, {%0,%1,%2,%3};"
        : "+f"(c[0]), "+f"(c[1]), "+f"(c[2]), "+f"(c[3])
        : "r"(a[0]), "r"(a[1]), "r"(a[2]), "r"(a[3]), "r"(b[0]), "r"(b[1]));
}

__global__ __launch_bounds__(256) void gemm_tc_kernel(
    const float* __restrict__ A, const float* __restrict__ B,
    const float* __restrict__ bias,
    const float* __restrict__ tscale, const float* __restrict__ tshift,
    float* __restrict__ C_, int M, int K, int N)
{
    __shared__ float As[GBK][GBM + 4];
    __shared__ float Bs[GBK][GBN + 4];
    int tid = threadIdx.x;
    int warp = tid >> 5, lane = tid & 31;
    int wm = warp & 3, wn = warp >> 2;
    int row0 = blockIdx.y * GBM;
    int col0 = blockIdx.x * GBN;
    int g = lane >> 2, t4 = lane & 3;

    float c[2][4][4];
    #pragma unroll
    for (int mm = 0; mm < 2; mm++)
        #pragma unroll
        for (int nn = 0; nn < 4; nn++)
            #pragma unroll
            for (int q = 0; q < 4; q++) c[mm][nn][q] = 0.f;

    for (int k0 = 0; k0 < K; k0 += GBK) {
        #pragma unroll
        for (int i = 0; i < 2; i++) {
            int idx = tid + 256 * i;
            int r = idx >> 2, c4 = idx & 3;
            int gr = row0 + r;
            float4 v = make_float4(0.f, 0.f, 0.f, 0.f);
            if (gr < M) v = *(const float4*)&A[(size_t)gr * K + k0 + c4 * 4];
            if (tscale) {
                int kb = k0 + c4 * 4;
                v.x = fmaxf(v.x * tscale[kb+0] + tshift[kb+0], 0.f);
                v.y = fmaxf(v.y * tscale[kb+1] + tshift[kb+1], 0.f);
                v.z = fmaxf(v.z * tscale[kb+2] + tshift[kb+2], 0.f);
                v.w = fmaxf(v.w * tscale[kb+3] + tshift[kb+3], 0.f);
            }
            As[c4*4+0][r] = v.x; As[c4*4+1][r] = v.y;
            As[c4*4+2][r] = v.z; As[c4*4+3][r] = v.w;
        }
        #pragma unroll
        for (int i = 0; i < 4; i++) {
            int idx = tid + 256 * i;
            int r = idx >> 6, cc = idx & 63;
            int gc = col0 + cc;
            float v = 0.f;
            if (gc < N) v = B[(size_t)(k0 + r) * N + gc];
            Bs[r][cc] = v;
        }
        __syncthreads();

        #pragma unroll
        for (int ks = 0; ks < GBK; ks += 8) {
            unsigned ahi[2][4], alo[2][4], bhi[4][2], blo[4][2];
            #pragma unroll
            for (int mm = 0; mm < 2; mm++) {
                int mrow = wm * 32 + mm * 16 + g;
                split_tf32(As[ks + t4][mrow],        ahi[mm][0], alo[mm][0]);
                split_tf32(As[ks + t4][mrow + 8],    ahi[mm][1], alo[mm][1]);
                split_tf32(As[ks + t4 + 4][mrow],    ahi[mm][2], alo[mm][2]);
                split_tf32(As[ks + t4 + 4][mrow + 8],ahi[mm][3], alo[mm][3]);
            }
            #pragma unroll
            for (int nn = 0; nn < 4; nn++) {
                int ncol = wn * 32 + nn * 8 + g;
                split_tf32(Bs[ks + t4][ncol],     bhi[nn][0], blo[nn][0]);
                split_tf32(Bs[ks + t4 + 4][ncol], bhi[nn][1], blo[nn][1]);
            }
            #pragma unroll
            for (int mm = 0; mm < 2; mm++)
                #pragma unroll
                for (int nn = 0; nn < 4; nn++) {
                    mma_tf32(c[mm][nn], ahi[mm], bhi[nn]);
                    mma_tf32(c[mm][nn], alo[mm], bhi[nn]);
                    mma_tf32(c[mm][nn], ahi[mm], blo[nn]);
                }
        }
        __syncthreads();
    }

    #pragma unroll
    for (int mm = 0; mm < 2; mm++) {
        int rbase = row0 + wm * 32 + mm * 16 + g;
        #pragma unroll
        for (int nn = 0; nn < 4; nn++) {
            int cbase = col0 + wn * 32 + nn * 8 + t4 * 2;
            #pragma unroll
            for (int q = 0; q < 4; q++) {
                int rr = rbase + ((q >= 2) ? 8 : 0);
                int cc = cbase + (q & 1);
                if (rr < M && cc < N) {
                    float v = c[mm][nn][q];
                    if (bias) v += bias[cc];
                    C_[(size_t)rr * N + cc] = v;
                }
            }
        }
    }
}

// ---------------- attention scores (float4) ----------------
__global__ void scores_kernel(const float* __restrict__ h, const float* __restrict__ a_s,
                              const float* __restrict__ a_d, float* ssrc, float* sdst,
                              int M, int H, int C4) {
    int t = blockIdx.x * blockDim.x + threadIdx.x;
    if (t >= M * H) return;
    int n = t / H, hh = t % H;
    const float4* hr = (const float4*)(h) + (size_t)n * H * C4 + hh * C4;
    const float4* as = (const float4*)(a_s) + hh * C4;
    const float4* ad = (const float4*)(a_d) + hh * C4;
    float s1 = 0.f, s2 = 0.f;
    for (int cc = 0; cc < C4; cc++) {
        float4 v = __ldg(&hr[cc]);
        float4 a = as[cc], d = ad[cc];
        s1 += v.x*a.x + v.y*a.y + v.z*a.z + v.w*a.w;
        s2 += v.x*d.x + v.y*d.y + v.z*d.z + v.w*d.w;
    }
    ssrc[t] = s1; sdst[t] = s2;
}

// ---------------- pass A: exp + z per node (no max: scores are small) ------
template <int H, int EPW>
__global__ void gat_softmax_kernel(const float* __restrict__ ssrc,
                                   const float* __restrict__ sdst,
                                   const int* __restrict__ off,
                                   const int* __restrict__ csr_src,
                                   float* __restrict__ alpha,
                                   float* __restrict__ zinv, int M) {
    constexpr int HP = 32 / EPW;
    int warp = (blockIdx.x * blockDim.x + threadIdx.x) >> 5;
    int lane = threadIdx.x & 31;
    if (warp >= M) return;
    int i = warp;
    int sub = lane / HP, hh = lane % HP;
    bool hvalid = (hh < H);
    int beg = off[i], end = off[i + 1];
    int deg = end - beg;

    float sd = hvalid ? sdst[(size_t)i * H + hh] : 0.f;
    float z = 0.f;
    for (int k = sub; k < deg; k += EPW) {
        int p = beg + k;
        int s = __ldg(&csr_src[p]);
        if (hvalid) {
            float v = ssrc[(size_t)s * H + hh] + sd;
            v = (v > 0.f) ? v : NEG_SLOPE * v;
            float e = __expf(v);
            alpha[(size_t)p * H + hh] = e;
            z += e;
        }
    }
    #pragma unroll
    for (int st = HP; st < 32; st <<= 1) z += __shfl_xor_sync(0xffffffffu, z, st);
    if (sub == 0 && hvalid) zinv[(size_t)i * H + hh] = 1.f / (z + 1e-16f);
}

// ---------------- chunked weighted aggregation (L2-resident gathers) ------
template <int H, int C, int CHUNK>
__global__ void gat_chunk_kernel(const float* __restrict__ h,
                                 const float* __restrict__ alpha,
                                 const float* __restrict__ zinv,
                                 const int* __restrict__ off,
                                 const int* __restrict__ csr_src,
                                 const float* __restrict__ bias,
                                 float* __restrict__ out, int M) {
    constexpr int HC = H * C;
    constexpr int F = CHUNK / 32;
    int warp = (blockIdx.x * blockDim.x + threadIdx.x) >> 5;
    int lane = threadIdx.x & 31;
    if (warp >= M) return;
    int i = warp;
    int c0 = blockIdx.y * CHUNK;
    int beg = off[i], end = off[i + 1];

    float zi = (lane < H) ? zinv[(size_t)i * H + lane] : 0.f;
    int hd[F];
    float acc[F];
    #pragma unroll
    for (int j = 0; j < F; j++) { hd[j] = (c0 + lane + 32 * j) / C; acc[j] = 0.f; }

    for (int p = beg; p < end; p++) {
        int s = __ldg(&csr_src[p]);
        float wl = (lane < H) ? alpha[(size_t)p * H + lane] * zi : 0.f;
        const float* hrow = h + (size_t)s * HC + c0;
        #pragma unroll
        for (int j = 0; j < F; j++) {
            float a = __shfl_sync(0xffffffffu, wl, hd[j]);
            acc[j] += a * __ldg(&hrow[lane + 32 * j]);
        }
    }
    float* orow = out + (size_t)i * HC + c0;
    #pragma unroll
    for (int j = 0; j < F; j++) {
        int idx = lane + 32 * j;
        orow[idx] = acc[j] + bias[c0 + idx];
    }
}

// ---------------- BatchNorm stats (atomic-free, 2-level) ----------------
__global__ void bn_stats_kernel(const float* __restrict__ X, int M, int D,
                                float* psum, float* psq) {
    int f = blockIdx.y * 128 + threadIdx.x;
    if (f >= D) return;
    int r0 = blockIdx.x * BN_ROWS;
    int rend = min(r0 + BN_ROWS, M);
    float s = 0.f, s2 = 0.f;
    for (int r = r0; r < rend; r++) {
        float v = X[(size_t)r * D + f];
        s += v; s2 += v * v;
    }
    psum[blockIdx.x * D + f] = s;
    psq [blockIdx.x * D + f] = s2;
}

__global__ void bn_finalize_kernel(const float* __restrict__ psum, const float* __restrict__ psq,
                                   const float* __restrict__ g, const float* __restrict__ be,
                                   float* scale, float* shift, int M, int D, int nchunks) {
    int f = blockIdx.x * blockDim.x + threadIdx.x;
    if (f >= D) return;
    float s = 0.f, s2 = 0.f;
    for (int c = 0; c < nchunks; c++) { s += psum[c * D + f]; s2 += psq[c * D + f]; }
    float inv = 1.f / (float)M;
    float mu = s * inv;
    float var = s2 * inv - mu * mu;
    float sc = g[f] * rsqrtf(var + EPS_BN);
    scale[f] = sc;
    shift[f] = be[f] - mu * sc;
}

// ---------------- pooling: segmented (batch sorted) + BN3+ReLU ----------
#define POOL_ROWS 512
__global__ void pool_bn_kernel(const float* __restrict__ h, const int* __restrict__ batch,
                               const float* __restrict__ scale, const float* __restrict__ shift,
                               float* pool, int* cnt, int M) {
    const int D = 384;
    int f = threadIdx.x;           // 384 threads
    int r0 = blockIdx.x * POOL_ROWS;
    int rend = min(r0 + POOL_ROWS, M);
    float sc = scale[f], sh = shift[f];
    int cur = __ldg(&batch[r0]);
    float acc = 0.f;
    int count = 0;
    for (int r = r0; r < rend; r++) {
        int b = __ldg(&batch[r]);
        if (b != cur) {
            atomicAdd(&pool[cur * D + f], acc);
            if (f == 0) atomicAdd(&cnt[cur], count);
            acc = 0.f; count = 0; cur = b;
        }
        acc += fmaxf(h[(size_t)r * D + f] * sc + sh, 0.f);
        count++;
    }
    atomicAdd(&pool[cur * D + f], acc);
    if (f == 0) atomicAdd(&cnt[cur], count);
}

__global__ void pool_div_kernel(float* pooled, const float* pool, const int* cnt, int G, int D) {
    int t = blockIdx.x * blockDim.x + threadIdx.x;
    if (t >= G * D) return;
    int g = t / D;
    float c = fmaxf((float)cnt[g], 1.f);
    pooled[t] = pool[t] / c;
}

// ---------------- host-side orchestration ----------------
struct Ptrs {
    float *h, *agg, *lin, *ssrc, *sdst, *alpha, *zinv;
    int *deg, *off, *cursor, *csr, *partial;
    float *bnpsum, *bnpsq, *scale, *shift, *pool, *pooled;
    int *cnt;
};

static void launch_gemm(const float* A, const float* B, const float* bias,
                        const float* tscale, const float* tshift, float* C,
                        int M, int K, int N) {
    dim3 grid((N + GBN - 1) / GBN, (M + GBM - 1) / GBM);
    gemm_tc_kernel<<<grid, 256>>>(A, B, bias, tscale, tshift, C, M, K, N);
}

static void run_bn_stats(const float* X, int M, int D, const float* g, const float* be, Ptrs& P) {
    int nchunks = (M + BN_ROWS - 1) / BN_ROWS;
    dim3 sg(nchunks, (D + 127) / 128);
    bn_stats_kernel<<<sg, 128>>>(X, M, D, P.bnpsum, P.bnpsq);
    bn_finalize_kernel<<<(D + 127) / 128, 128>>>(P.bnpsum, P.bnpsq, g, be, P.scale, P.shift, M, D, nchunks);
}

extern "C" void kernel_launch(void* const* d_in, const int* in_sizes, int n_in,
                              void* d_out, int out_size) {
    const float* x     = (const float*)d_in[0];
    const int*   ei    = (const int*)  d_in[1];
    const int*   batch = (const int*)  d_in[2];
    const float* W1  = (const float*)d_in[3];
    const float* as1 = (const float*)d_in[4];
    const float* ad1 = (const float*)d_in[5];
    const float* b1  = (const float*)d_in[6];
    const float* g1  = (const float*)d_in[7];
    const float* be1 = (const float*)d_in[8];
    const float* lw1 = (const float*)d_in[9];
    const float* lb1 = (const float*)d_in[10];
    const float* gl1 = (const float*)d_in[11];
    const float* bel1= (const float*)d_in[12];
    const float* W2  = (const float*)d_in[13];
    const float* as2 = (const float*)d_in[14];
    const float* ad2 = (const float*)d_in[15];
    const float* b2  = (const float*)d_in[16];
    const float* g2  = (const float*)d_in[17];
    const float* be2 = (const float*)d_in[18];
    const float* lw2 = (const float*)d_in[19];
    const float* lb2 = (const float*)d_in[20];
    const float* gl2 = (const float*)d_in[21];
    const float* bel2= (const float*)d_in[22];
    const float* W3  = (const float*)d_in[23];
    const float* as3 = (const float*)d_in[24];
    const float* ad3 = (const float*)d_in[25];
    const float* b3  = (const float*)d_in[26];
    const float* g3  = (const float*)d_in[27];
    const float* be3 = (const float*)d_in[28];
    const float* lwf = (const float*)d_in[29];
    const float* lbf = (const float*)d_in[30];

    int M = in_sizes[2];
    int E = in_sizes[1] / 2;
    int EX = E + M;

    Ptrs P;
    cudaGetSymbolAddress((void**)&P.h, d_h);
    cudaGetSymbolAddress((void**)&P.agg, d_agg);
    cudaGetSymbolAddress((void**)&P.lin, d_lin);
    cudaGetSymbolAddress((void**)&P.ssrc, d_ssrc);
    cudaGetSymbolAddress((void**)&P.sdst, d_sdst);
    cudaGetSymbolAddress((void**)&P.alpha, d_alpha);
    cudaGetSymbolAddress((void**)&P.zinv, d_zinv);
    cudaGetSymbolAddress((void**)&P.deg, d_deg);
    cudaGetSymbolAddress((void**)&P.off, d_off);
    cudaGetSymbolAddress((void**)&P.cursor, d_cursor);
    cudaGetSymbolAddress((void**)&P.csr, d_csr);
    cudaGetSymbolAddress((void**)&P.partial, d_partial);
    cudaGetSymbolAddress((void**)&P.bnpsum, d_bnpsum);
    cudaGetSymbolAddress((void**)&P.bnpsq, d_bnpsq);
    cudaGetSymbolAddress((void**)&P.scale, d_scale);
    cudaGetSymbolAddress((void**)&P.shift, d_shift);
    cudaGetSymbolAddress((void**)&P.pool, d_pool);
    cudaGetSymbolAddress((void**)&P.pooled, d_pooled);
    cudaGetSymbolAddress((void**)&P.cnt, d_cnt);

    // ---- CSR build (shared by all three GAT layers) ----
    zero_i_kernel<<<(M + 255) / 256, 256>>>(P.deg, M);
    edge_hist_kernel<<<(EX + 255) / 256, 256>>>(ei, E, M, P.deg);
    int nb = (M + 1023) / 1024;
    scan_block_kernel<<<nb, 1024>>>(P.deg, P.off, P.partial, M);
    scan_add_kernel<<<(M + 255) / 256, 256>>>(P.off, P.partial, P.cursor, M, EX);
    edge_scatter_kernel<<<(EX + 255) / 256, 256>>>(ei, E, M, P.cursor, P.csr);

    const int wpb = 8;
    int ablk = (M + wpb - 1) / wpb;

    // ---- Layer 1: GAT(128 -> 20x16=320) ----
    launch_gemm(x, W1, nullptr, nullptr, nullptr, P.h, M, 128, 320);
    scores_kernel<<<(M * 20 + 255) / 256, 256>>>(P.h, as1, ad1, P.ssrc, P.sdst, M, 20, 4);
    gat_softmax_kernel<20, 1><<<ablk, wpb * 32>>>(P.ssrc, P.sdst, P.off, P.csr, P.alpha, P.zinv, M);
    gat_chunk_kernel<20, 16, 160><<<dim3(ablk, 2), wpb * 32>>>(P.h, P.alpha, P.zinv, P.off, P.csr, b1, P.agg, M);
    run_bn_stats(P.agg, M, 320, g1, be1, P);
    launch_gemm(P.agg, lw1, lb1, P.scale, P.shift, P.lin, M, 320, 16);
    run_bn_stats(P.lin, M, 16, gl1, bel1, P);

    // ---- Layer 2: GAT(16 -> 16x32=512) ----
    launch_gemm(P.lin, W2, nullptr, P.scale, P.shift, P.h, M, 16, 512);
    scores_kernel<<<(M * 16 + 255) / 256, 256>>>(P.h, as2, ad2, P.ssrc, P.sdst, M, 16, 8);
    gat_softmax_kernel<16, 2><<<ablk, wpb * 32>>>(P.ssrc, P.sdst, P.off, P.csr, P.alpha, P.zinv, M);
    gat_chunk_kernel<16, 32, 128><<<dim3(ablk, 4), wpb * 32>>>(P.h, P.alpha, P.zinv, P.off, P.csr, b2, P.agg, M);
    run_bn_stats(P.agg, M, 512, g2, be2, P);
    launch_gemm(P.agg, lw2, lb2, P.scale, P.shift, P.lin, M, 512, 32);
    run_bn_stats(P.lin, M, 32, gl2, bel2, P);

    // ---- Layer 3: GAT(32 -> 8x48=384) ----
    launch_gemm(P.lin, W3, nullptr, P.scale, P.shift, P.h, M, 32, 384);
    scores_kernel<<<(M * 8 + 255) / 256, 256>>>(P.h, as3, ad3, P.ssrc, P.sdst, M, 8, 12);
    gat_softmax_kernel<8, 4><<<ablk, wpb * 32>>>(P.ssrc, P.sdst, P.off, P.csr, P.alpha, P.zinv, M);
    gat_chunk_kernel<8, 48, 192><<<dim3(ablk, 2), wpb * 32>>>(P.h, P.alpha, P.zinv, P.off, P.csr, b3, P.agg, M);
    run_bn_stats(P.agg, M, 384, g3, be3, P);

    // ---- global mean pool (fused BN3+ReLU, segmented) + final linear ----
    zero_pool_kernel<<<(GG * 384 + 255) / 256, 256>>>(P.pool, P.cnt);
    pool_bn_kernel<<<(M + POOL_ROWS - 1) / POOL_ROWS, 384>>>(P.agg, batch, P.scale, P.shift, P.pool, P.cnt, M);
    pool_div_kernel<<<(GG * 384 + 255) / 256, 256>>>(P.pooled, P.pool, P.cnt, GG, 384);
    launch_gemm(P.pooled, lwf, lbf, nullptr, nullptr, (float*)d_out, GG, 384, 10);
}

// round 7
// speedup vs baseline: 1.5485x; 1.1239x over previous
#include <cuda_runtime.h>
#include <cuda_bf16.h>
#include <math.h>

// ---------------- problem constants ----------------
#define NN   50000
#define EEX  450000
#define GG   64
#define DMAX 544     // max HC+2H (layer2: 512+32)
#define EPS_BN 1e-5f
#define NEG_SLOPE 0.2f
#define BN_ROWS 512

// ---------------- static scratch ----------------
__device__ float d_hx [(size_t)NN * DMAX];   // [h | s_src | s_dst] per row
__device__ float d_agg[(size_t)NN * 512];
__device__ float d_lin[(size_t)NN * 64];
__device__ float d_bcat[128 * DMAX];         // concatenated B
__device__ int   d_deg[NN];
__device__ int   d_off[NN + 1];
__device__ int   d_cursor[NN];
__device__ int   d_csr[EEX];
__device__ int   d_partial[128];
__device__ float d_bnpsum[128 * 512];
__device__ float d_bnpsq [128 * 512];
__device__ float d_scale[512];
__device__ float d_shift[512];
__device__ float d_pool[GG * 384];
__device__ int   d_cnt [GG];
__device__ float d_pooled[GG * 384];

// ---------------- small utility kernels ----------------
__global__ void zero_i_kernel(int* p, int n) {
    int t = blockIdx.x * blockDim.x + threadIdx.x;
    if (t < n) p[t] = 0;
}
__global__ void zero_pool_kernel(float* pool, int* cnt) {
    int t = blockIdx.x * blockDim.x + threadIdx.x;
    if (t < GG * 384) pool[t] = 0.f;
    if (t < GG) cnt[t] = 0;
}

// ---------------- CSR build ----------------
__global__ void edge_hist_kernel(const int* __restrict__ ei, int E, int n, int* deg) {
    int t = blockIdx.x * blockDim.x + threadIdx.x;
    int total = E + n;
    if (t >= total) return;
    int dst = (t < E) ? ei[E + t] : (t - E);
    atomicAdd(&deg[dst], 1);
}

__global__ void scan_block_kernel(const int* __restrict__ deg, int* off, int* partial, int n) {
    __shared__ int sm[1024];
    int gid = blockIdx.x * 1024 + threadIdx.x;
    int v = (gid < n) ? deg[gid] : 0;
    sm[threadIdx.x] = v;
    __syncthreads();
    for (int d = 1; d < 1024; d <<= 1) {
        int t = (threadIdx.x >= d) ? sm[threadIdx.x - d] : 0;
        __syncthreads();
        sm[threadIdx.x] += t;
        __syncthreads();
    }
    if (gid < n) off[gid] = sm[threadIdx.x] - v;
    if (threadIdx.x == 1023) partial[blockIdx.x] = sm[1023];
}

__global__ void scan_add_kernel(int* off, const int* __restrict__ partial, int* cursor,
                                int n, int total) {
    int gid = blockIdx.x * blockDim.x + threadIdx.x;
    if (gid < n) {
        int pb = gid >> 10;
        int base = 0;
        for (int j = 0; j < pb; j++) base += partial[j];
        int v = off[gid] + base;
        off[gid] = v;
        cursor[gid] = v;
    }
    if (gid == 0) off[n] = total;
}

__global__ void edge_scatter_kernel(const int* __restrict__ ei, int E, int n,
                                    int* cursor, int* csr_src) {
    int t = blockIdx.x * blockDim.x + threadIdx.x;
    int total = E + n;
    if (t >= total) return;
    int src, dst;
    if (t < E) { src = ei[t]; dst = ei[E + t]; }
    else       { src = t - E; dst = t - E; }
    int pos = atomicAdd(&cursor[dst], 1);
    csr_src[pos] = src;
}

// ---------------- build concatenated B = [W | Wa_src | Wa_dst] ----------
__global__ void build_bcat_kernel(const float* __restrict__ W,
                                  const float* __restrict__ a_s,
                                  const float* __restrict__ a_d,
                                  float* __restrict__ bcat, int K, int H, int C) {
    int HC = H * C;
    int NC = HC + 2 * H;
    int idx = blockIdx.x * blockDim.x + threadIdx.x;
    if (idx >= K * NC) return;
    int k = idx / NC, col = idx % NC;
    if (col < HC) {
        bcat[idx] = W[(size_t)k * HC + col];
    } else {
        int hh = col - HC;
        const float* a = (hh >= H) ? a_d : a_s;
        if (hh >= H) hh -= H;
        float s = 0.f;
        for (int c = 0; c < C; c++) s += W[(size_t)k * HC + hh * C + c] * a[hh * C + c];
        bcat[idx] = s;
    }
}

// ---------------- tensor-core GEMM (3xTF32 for fp32 accuracy) ----------------
#define GBM 128
#define GBN 64
#define GBK 16

__device__ __forceinline__ void split_tf32(float x, unsigned& hi, unsigned& lo) {
    unsigned h_;
    asm("cvt.rna.tf32.f32 %0, %1;" : "=r"(h_) : "f"(x));
    float lf = x - __uint_as_float(h_);
    unsigned l_;
    asm("cvt.rna.tf32.f32 %0, %1;" : "=r"(l_) : "f"(lf));
    hi = h_; lo = l_;
}

__device__ __forceinline__ void mma_tf32(float c[4], const unsigned a[4], const unsigned b[2]) {
    asm volatile(
        "mma.sync.aligned.m16n8k8.row.col.f32.tf32.tf32.f32 "
        "{%0,%1,%2,%3}, {%4,%5,%6,%7}, {%8,%9}, {%0,%1,%2,%3};"
        : "+f"(c[0]), "+f"(c[1]), "+f"(c[2]), "+f"(c[3])
        : "r"(a[0]), "r"(a[1]), "r"(a[2]), "r"(a[3]), "r"(b[0]), "r"(b[1]));
}

__global__ __launch_bounds__(256) void gemm_tc_kernel(
    const float* __restrict__ A, const float* __restrict__ B,
    const float* __restrict__ bias,
    const float* __restrict__ tscale, const float* __restrict__ tshift,
    float* __restrict__ C_, int M, int K, int N)
{
    __shared__ float As[GBK][GBM + 4];
    __shared__ float Bs[GBK][GBN + 4];
    int tid = threadIdx.x;
    int warp = tid >> 5, lane = tid & 31;
    int wm = warp & 3, wn = warp >> 2;
    int row0 = blockIdx.y * GBM;
    int col0 = blockIdx.x * GBN;
    int g = lane >> 2, t4 = lane & 3;

    float c[2][4][4];
    #pragma unroll
    for (int mm = 0; mm < 2; mm++)
        #pragma unroll
        for (int nn = 0; nn < 4; nn++)
            #pragma unroll
            for (int q = 0; q < 4; q++) c[mm][nn][q] = 0.f;

    for (int k0 = 0; k0 < K; k0 += GBK) {
        #pragma unroll
        for (int i = 0; i < 2; i++) {
            int idx = tid + 256 * i;
            int r = idx >> 2, c4 = idx & 3;
            int gr = row0 + r;
            float4 v = make_float4(0.f, 0.f, 0.f, 0.f);
            if (gr < M) v = *(const float4*)&A[(size_t)gr * K + k0 + c4 * 4];
            if (tscale) {
                int kb = k0 + c4 * 4;
                v.x = fmaxf(v.x * tscale[kb+0] + tshift[kb+0], 0.f);
                v.y = fmaxf(v.y * tscale[kb+1] + tshift[kb+1], 0.f);
                v.z = fmaxf(v.z * tscale[kb+2] + tshift[kb+2], 0.f);
                v.w = fmaxf(v.w * tscale[kb+3] + tshift[kb+3], 0.f);
            }
            As[c4*4+0][r] = v.x; As[c4*4+1][r] = v.y;
            As[c4*4+2][r] = v.z; As[c4*4+3][r] = v.w;
        }
        #pragma unroll
        for (int i = 0; i < 4; i++) {
            int idx = tid + 256 * i;
            int r = idx >> 6, cc = idx & 63;
            int gc = col0 + cc;
            float v = 0.f;
            if (gc < N) v = B[(size_t)(k0 + r) * N + gc];
            Bs[r][cc] = v;
        }
        __syncthreads();

        #pragma unroll
        for (int ks = 0; ks < GBK; ks += 8) {
            unsigned ahi[2][4], alo[2][4], bhi[4][2], blo[4][2];
            #pragma unroll
            for (int mm = 0; mm < 2; mm++) {
                int mrow = wm * 32 + mm * 16 + g;
                split_tf32(As[ks + t4][mrow],        ahi[mm][0], alo[mm][0]);
                split_tf32(As[ks + t4][mrow + 8],    ahi[mm][1], alo[mm][1]);
                split_tf32(As[ks + t4 + 4][mrow],    ahi[mm][2], alo[mm][2]);
                split_tf32(As[ks + t4 + 4][mrow + 8],ahi[mm][3], alo[mm][3]);
            }
            #pragma unroll
            for (int nn = 0; nn < 4; nn++) {
                int ncol = wn * 32 + nn * 8 + g;
                split_tf32(Bs[ks + t4][ncol],     bhi[nn][0], blo[nn][0]);
                split_tf32(Bs[ks + t4 + 4][ncol], bhi[nn][1], blo[nn][1]);
            }
            #pragma unroll
            for (int mm = 0; mm < 2; mm++)
                #pragma unroll
                for (int nn = 0; nn < 4; nn++) {
                    mma_tf32(c[mm][nn], ahi[mm], bhi[nn]);
                    mma_tf32(c[mm][nn], alo[mm], bhi[nn]);
                    mma_tf32(c[mm][nn], ahi[mm], blo[nn]);
                }
        }
        __syncthreads();
    }

    #pragma unroll
    for (int mm = 0; mm < 2; mm++) {
        int rbase = row0 + wm * 32 + mm * 16 + g;
        #pragma unroll
        for (int nn = 0; nn < 4; nn++) {
            int cbase = col0 + wn * 32 + nn * 8 + t4 * 2;
            #pragma unroll
            for (int q = 0; q < 4; q++) {
                int rr = rbase + ((q >= 2) ? 8 : 0);
                int cc = cbase + (q & 1);
                if (rr < M && cc < N) {
                    float v = c[mm][nn][q];
                    if (bias) v += bias[cc];
                    C_[(size_t)rr * N + cc] = v;
                }
            }
        }
    }
}

// ---------------- fused single-pass GAT aggregation ----------------
// hx rows: [h(HC) | s_src(H) | s_dst(H)], stride NSTR = HC+2H.
template <int H, int C>
__global__ void gat_aggregate_kernel(const float* __restrict__ hx,
                                     const int* __restrict__ off,
                                     const int* __restrict__ csr_src,
                                     const float* __restrict__ bias,
                                     float* __restrict__ out, int M) {
    constexpr int HC = H * C;
    constexpr int NSTR = HC + 2 * H;
    constexpr int N2 = HC / 64;
    int warp = (blockIdx.x * blockDim.x + threadIdx.x) >> 5;
    int lane = threadIdx.x & 31;
    if (warp >= M) return;
    int i = warp;
    int beg = off[i], end = off[i + 1];

    float sd = (lane < H) ? hx[(size_t)i * NSTR + HC + H + lane] : 0.f;
    float z = 0.f;
    float2 acc[N2];
    int hd[N2];
    #pragma unroll
    for (int j = 0; j < N2; j++) {
        acc[j] = make_float2(0.f, 0.f);
        hd[j] = (2 * (lane + 32 * j)) / C;
    }

    for (int p = beg; p < end; p++) {
        int s = __ldg(&csr_src[p]);
        const float* row = hx + (size_t)s * NSTR;
        float ev = 0.f;
        if (lane < H) {
            float v = __ldg(&row[HC + lane]) + sd;
            v = (v > 0.f) ? v : NEG_SLOPE * v;
            ev = __expf(v);
            z += ev;
        }
        const float2* hrow = (const float2*)row;
        #pragma unroll
        for (int j = 0; j < N2; j++) {
            float a = __shfl_sync(0xffffffffu, ev, hd[j]);
            float2 hv = __ldg(&hrow[lane + 32 * j]);
            acc[j].x += a * hv.x;
            acc[j].y += a * hv.y;
        }
    }
    float zinv = (lane < H) ? 1.f / (z + 1e-16f) : 0.f;
    const float2* b2 = (const float2*)bias;
    float2* o2 = (float2*)(out + (size_t)i * HC);
    #pragma unroll
    for (int j = 0; j < N2; j++) {
        float zi = __shfl_sync(0xffffffffu, zinv, hd[j]);
        int idx = lane + 32 * j;
        float2 bb = b2[idx];
        o2[idx] = make_float2(acc[j].x * zi + bb.x, acc[j].y * zi + bb.y);
    }
}

// ---------------- BatchNorm stats (atomic-free, 2-level) ----------------
__global__ void bn_stats_kernel(const float* __restrict__ X, int M, int D,
                                float* psum, float* psq) {
    int f = blockIdx.y * 128 + threadIdx.x;
    if (f >= D) return;
    int r0 = blockIdx.x * BN_ROWS;
    int rend = min(r0 + BN_ROWS, M);
    float s = 0.f, s2 = 0.f;
    for (int r = r0; r < rend; r++) {
        float v = X[(size_t)r * D + f];
        s += v; s2 += v * v;
    }
    psum[blockIdx.x * D + f] = s;
    psq [blockIdx.x * D + f] = s2;
}

__global__ void bn_finalize_kernel(const float* __restrict__ psum, const float* __restrict__ psq,
                                   const float* __restrict__ g, const float* __restrict__ be,
                                   float* scale, float* shift, int M, int D, int nchunks) {
    int f = blockIdx.x * blockDim.x + threadIdx.x;
    if (f >= D) return;
    float s = 0.f, s2 = 0.f;
    for (int c = 0; c < nchunks; c++) { s += psum[c * D + f]; s2 += psq[c * D + f]; }
    float inv = 1.f / (float)M;
    float mu = s * inv;
    float var = s2 * inv - mu * mu;
    float sc = g[f] * rsqrtf(var + EPS_BN);
    scale[f] = sc;
    shift[f] = be[f] - mu * sc;
}

// ---------------- pooling: segmented (batch sorted) + BN3+ReLU ----------
#define POOL_ROWS 512
__global__ void pool_bn_kernel(const float* __restrict__ h, const int* __restrict__ batch,
                               const float* __restrict__ scale, const float* __restrict__ shift,
                               float* pool, int* cnt, int M) {
    const int D = 384;
    int f = threadIdx.x;
    int r0 = blockIdx.x * POOL_ROWS;
    int rend = min(r0 + POOL_ROWS, M);
    float sc = scale[f], sh = shift[f];
    int cur = __ldg(&batch[r0]);
    float acc = 0.f;
    int count = 0;
    for (int r = r0; r < rend; r++) {
        int b = __ldg(&batch[r]);
        if (b != cur) {
            atomicAdd(&pool[cur * D + f], acc);
            if (f == 0) atomicAdd(&cnt[cur], count);
            acc = 0.f; count = 0; cur = b;
        }
        acc += fmaxf(h[(size_t)r * D + f] * sc + sh, 0.f);
        count++;
    }
    atomicAdd(&pool[cur * D + f], acc);
    if (f == 0) atomicAdd(&cnt[cur], count);
}

__global__ void pool_div_kernel(float* pooled, const float* pool, const int* cnt, int G, int D) {
    int t = blockIdx.x * blockDim.x + threadIdx.x;
    if (t >= G * D) return;
    int g = t / D;
    float c = fmaxf((float)cnt[g], 1.f);
    pooled[t] = pool[t] / c;
}

// ---------------- host-side orchestration ----------------
struct Ptrs {
    float *hx, *agg, *lin, *bcat;
    int *deg, *off, *cursor, *csr, *partial;
    float *bnpsum, *bnpsq, *scale, *shift, *pool, *pooled;
    int *cnt;
};

static void launch_gemm(const float* A, const float* B, const float* bias,
                        const float* tscale, const float* tshift, float* C,
                        int M, int K, int N) {
    dim3 grid((N + GBN - 1) / GBN, (M + GBM - 1) / GBM);
    gemm_tc_kernel<<<grid, 256>>>(A, B, bias, tscale, tshift, C, M, K, N);
}

static void run_bn_stats(const float* X, int M, int D, const float* g, const float* be, Ptrs& P) {
    int nchunks = (M + BN_ROWS - 1) / BN_ROWS;
    dim3 sg(nchunks, (D + 127) / 128);
    bn_stats_kernel<<<sg, 128>>>(X, M, D, P.bnpsum, P.bnpsq);
    bn_finalize_kernel<<<(D + 127) / 128, 128>>>(P.bnpsum, P.bnpsq, g, be, P.scale, P.shift, M, D, nchunks);
}

extern "C" void kernel_launch(void* const* d_in, const int* in_sizes, int n_in,
                              void* d_out, int out_size) {
    const float* x     = (const float*)d_in[0];
    const int*   ei    = (const int*)  d_in[1];
    const int*   batch = (const int*)  d_in[2];
    const float* W1  = (const float*)d_in[3];
    const float* as1 = (const float*)d_in[4];
    const float* ad1 = (const float*)d_in[5];
    const float* b1  = (const float*)d_in[6];
    const float* g1  = (const float*)d_in[7];
    const float* be1 = (const float*)d_in[8];
    const float* lw1 = (const float*)d_in[9];
    const float* lb1 = (const float*)d_in[10];
    const float* gl1 = (const float*)d_in[11];
    const float* bel1= (const float*)d_in[12];
    const float* W2  = (const float*)d_in[13];
    const float* as2 = (const float*)d_in[14];
    const float* ad2 = (const float*)d_in[15];
    const float* b2  = (const float*)d_in[16];
    const float* g2  = (const float*)d_in[17];
    const float* be2 = (const float*)d_in[18];
    const float* lw2 = (const float*)d_in[19];
    const float* lb2 = (const float*)d_in[20];
    const float* gl2 = (const float*)d_in[21];
    const float* bel2= (const float*)d_in[22];
    const float* W3  = (const float*)d_in[23];
    const float* as3 = (const float*)d_in[24];
    const float* ad3 = (const float*)d_in[25];
    const float* b3  = (const float*)d_in[26];
    const float* g3  = (const float*)d_in[27];
    const float* be3 = (const float*)d_in[28];
    const float* lwf = (const float*)d_in[29];
    const float* lbf = (const float*)d_in[30];

    int M = in_sizes[2];
    int E = in_sizes[1] / 2;
    int EX = E + M;

    Ptrs P;
    cudaGetSymbolAddress((void**)&P.hx, d_hx);
    cudaGetSymbolAddress((void**)&P.agg, d_agg);
    cudaGetSymbolAddress((void**)&P.lin, d_lin);
    cudaGetSymbolAddress((void**)&P.bcat, d_bcat);
    cudaGetSymbolAddress((void**)&P.deg, d_deg);
    cudaGetSymbolAddress((void**)&P.off, d_off);
    cudaGetSymbolAddress((void**)&P.cursor, d_cursor);
    cudaGetSymbolAddress((void**)&P.csr, d_csr);
    cudaGetSymbolAddress((void**)&P.partial, d_partial);
    cudaGetSymbolAddress((void**)&P.bnpsum, d_bnpsum);
    cudaGetSymbolAddress((void**)&P.bnpsq, d_bnpsq);
    cudaGetSymbolAddress((void**)&P.scale, d_scale);
    cudaGetSymbolAddress((void**)&P.shift, d_shift);
    cudaGetSymbolAddress((void**)&P.pool, d_pool);
    cudaGetSymbolAddress((void**)&P.pooled, d_pooled);
    cudaGetSymbolAddress((void**)&P.cnt, d_cnt);

    // ---- CSR build ----
    zero_i_kernel<<<(M + 255) / 256, 256>>>(P.deg, M);
    edge_hist_kernel<<<(EX + 255) / 256, 256>>>(ei, E, M, P.deg);
    int nb = (M + 1023) / 1024;
    scan_block_kernel<<<nb, 1024>>>(P.deg, P.off, P.partial, M);
    scan_add_kernel<<<(M + 255) / 256, 256>>>(P.off, P.partial, P.cursor, M, EX);
    edge_scatter_kernel<<<(EX + 255) / 256, 256>>>(ei, E, M, P.cursor, P.csr);

    const int wpb = 8;
    int ablk = (M + wpb - 1) / wpb;

    // ---- Layer 1: GAT(128 -> 20x16=320), NC=360 ----
    build_bcat_kernel<<<(128 * 360 + 255) / 256, 256>>>(W1, as1, ad1, P.bcat, 128, 20, 16);
    launch_gemm(x, P.bcat, nullptr, nullptr, nullptr, P.hx, M, 128, 360);
    gat_aggregate_kernel<20, 16><<<ablk, wpb * 32>>>(P.hx, P.off, P.csr, b1, P.agg, M);
    run_bn_stats(P.agg, M, 320, g1, be1, P);
    launch_gemm(P.agg, lw1, lb1, P.scale, P.shift, P.lin, M, 320, 16);
    run_bn_stats(P.lin, M, 16, gl1, bel1, P);

    // ---- Layer 2: GAT(16 -> 16x32=512), NC=544 ----
    build_bcat_kernel<<<(16 * 544 + 255) / 256, 256>>>(W2, as2, ad2, P.bcat, 16, 16, 32);
    launch_gemm(P.lin, P.bcat, nullptr, P.scale, P.shift, P.hx, M, 16, 544);
    gat_aggregate_kernel<16, 32><<<ablk, wpb * 32>>>(P.hx, P.off, P.csr, b2, P.agg, M);
    run_bn_stats(P.agg, M, 512, g2, be2, P);
    launch_gemm(P.agg, lw2, lb2, P.scale, P.shift, P.lin, M, 512, 32);
    run_bn_stats(P.lin, M, 32, gl2, bel2, P);

    // ---- Layer 3: GAT(32 -> 8x48=384), NC=400 ----
    build_bcat_kernel<<<(32 * 400 + 255) / 256, 256>>>(W3, as3, ad3, P.bcat, 32, 8, 48);
    launch_gemm(P.lin, P.bcat, nullptr, P.scale, P.shift, P.hx, M, 32, 400);
    gat_aggregate_kernel<8, 48><<<ablk, wpb * 32>>>(P.hx, P.off, P.csr, b3, P.agg, M);
    run_bn_stats(P.agg, M, 384, g3, be3, P);

    // ---- global mean pool (fused BN3+ReLU, segmented) + final linear ----
    zero_pool_kernel<<<(GG * 384 + 255) / 256, 256>>>(P.pool, P.cnt);
    pool_bn_kernel<<<(M + POOL_ROWS - 1) / POOL_ROWS, 384>>>(P.agg, batch, P.scale, P.shift, P.pool, P.cnt, M);
    pool_div_kernel<<<(GG * 384 + 255) / 256, 256>>>(P.pooled, P.pool, P.cnt, GG, 384);
    launch_gemm(P.pooled, lwf, lbf, nullptr, nullptr, (float*)d_out, GG, 384, 10);
}

// round 9
// speedup vs baseline: 1.6527x; 1.0673x over previous
#include <cuda_runtime.h>
#include <cuda_bf16.h>
#include <math.h>

// ---------------- problem constants ----------------
#define NN   50000
#define EEX  450000
#define GG   64
#define DMAX 544
#define EPS_BN 1e-5f
#define NEG_SLOPE 0.2f
#define BN_ROWS 512

// ---------------- static scratch ----------------
__device__ float d_hx [(size_t)NN * DMAX];   // L1: [h|s_src|s_dst]; L2/3: scores [N,2H]
__device__ float d_agg[(size_t)NN * 512];
__device__ float d_lin[(size_t)NN * 64];
__device__ float d_aggx[(size_t)NN * 256];   // aggregated inputs for L2/L3
__device__ float d_bcat[128 * DMAX];
__device__ int   d_deg[NN];
__device__ int   d_off[NN + 1];
__device__ int   d_cursor[NN];
__device__ int   d_csr[EEX];
__device__ int   d_partial[128];
__device__ float d_bnpsum[128 * 512];
__device__ float d_bnpsq [128 * 512];
__device__ float d_scale[512];
__device__ float d_shift[512];
__device__ float d_pool[GG * 384];
__device__ int   d_cnt [GG];
__device__ float d_pooled[GG * 384];

// ---------------- small utility kernels ----------------
__global__ void zero_i_kernel(int* p, int n) {
    int t = blockIdx.x * blockDim.x + threadIdx.x;
    if (t < n) p[t] = 0;
}
__global__ void zero_pool_kernel(float* pool, int* cnt) {
    int t = blockIdx.x * blockDim.x + threadIdx.x;
    if (t < GG * 384) pool[t] = 0.f;
    if (t < GG) cnt[t] = 0;
}

// ---------------- CSR build ----------------
__global__ void edge_hist_kernel(const int* __restrict__ ei, int E, int n, int* deg) {
    int t = blockIdx.x * blockDim.x + threadIdx.x;
    int total = E + n;
    if (t >= total) return;
    int dst = (t < E) ? ei[E + t] : (t - E);
    atomicAdd(&deg[dst], 1);
}

__global__ void scan_block_kernel(const int* __restrict__ deg, int* off, int* partial, int n) {
    __shared__ int sm[1024];
    int gid = blockIdx.x * 1024 + threadIdx.x;
    int v = (gid < n) ? deg[gid] : 0;
    sm[threadIdx.x] = v;
    __syncthreads();
    for (int d = 1; d < 1024; d <<= 1) {
        int t = (threadIdx.x >= d) ? sm[threadIdx.x - d] : 0;
        __syncthreads();
        sm[threadIdx.x] += t;
        __syncthreads();
    }
    if (gid < n) off[gid] = sm[threadIdx.x] - v;
    if (threadIdx.x == 1023) partial[blockIdx.x] = sm[1023];
}

__global__ void scan_add_kernel(int* off, const int* __restrict__ partial, int* cursor,
                                int n, int total) {
    int gid = blockIdx.x * blockDim.x + threadIdx.x;
    if (gid < n) {
        int pb = gid >> 10;
        int base = 0;
        for (int j = 0; j < pb; j++) base += partial[j];
        int v = off[gid] + base;
        off[gid] = v;
        cursor[gid] = v;
    }
    if (gid == 0) off[n] = total;
}

__global__ void edge_scatter_kernel(const int* __restrict__ ei, int E, int n,
                                    int* cursor, int* csr_src) {
    int t = blockIdx.x * blockDim.x + threadIdx.x;
    int total = E + n;
    if (t >= total) return;
    int src, dst;
    if (t < E) { src = ei[t]; dst = ei[E + t]; }
    else       { src = t - E; dst = t - E; }
    int pos = atomicAdd(&cursor[dst], 1);
    csr_src[pos] = src;
}

// ---------------- build concatenated B = [W | Wa_src | Wa_dst] ----------
__global__ void build_bcat_kernel(const float* __restrict__ W,
                                  const float* __restrict__ a_s,
                                  const float* __restrict__ a_d,
                                  float* __restrict__ bcat, int K, int H, int C) {
    int HC = H * C;
    int NC = HC + 2 * H;
    int idx = blockIdx.x * blockDim.x + threadIdx.x;
    if (idx >= K * NC) return;
    int k = idx / NC, col = idx % NC;
    if (col < HC) {
        bcat[idx] = W[(size_t)k * HC + col];
    } else {
        int hh = col - HC;
        const float* a = (hh >= H) ? a_d : a_s;
        if (hh >= H) hh -= H;
        float s = 0.f;
        for (int c = 0; c < C; c++) s += W[(size_t)k * HC + hh * C + c] * a[hh * C + c];
        bcat[idx] = s;
    }
}

// ---------------- build score-only B = [Wa_src | Wa_dst]  (K x 2H) --------
__global__ void build_bsc_kernel(const float* __restrict__ W,
                                 const float* __restrict__ a_s,
                                 const float* __restrict__ a_d,
                                 float* __restrict__ bsc, int K, int H, int C) {
    int HC = H * C;
    int NC = 2 * H;
    int idx = blockIdx.x * blockDim.x + threadIdx.x;
    if (idx >= K * NC) return;
    int k = idx / NC, col = idx % NC;
    int hh = (col >= H) ? col - H : col;
    const float* a = (col >= H) ? a_d : a_s;
    float s = 0.f;
    for (int c = 0; c < C; c++) s += W[(size_t)k * HC + hh * C + c] * a[hh * C + c];
    bsc[idx] = s;
}

// ---------------- tensor-core GEMM (3xTF32 for fp32 accuracy) ----------------
#define GBM 128
#define GBN 64
#define GBK 16

__device__ __forceinline__ void split_tf32(float x, unsigned& hi, unsigned& lo) {
    unsigned h_;
    asm("cvt.rna.tf32.f32 %0, %1;" : "=r"(h_) : "f"(x));
    float lf = x - __uint_as_float(h_);
    unsigned l_;
    asm("cvt.rna.tf32.f32 %0, %1;" : "=r"(l_) : "f"(lf));
    hi = h_; lo = l_;
}

__device__ __forceinline__ void mma_tf32(float c[4], const unsigned a[4], const unsigned b[2]) {
    asm volatile(
        "mma.sync.aligned.m16n8k8.row.col.f32.tf32.tf32.f32 "
        "{%0,%1,%2,%3}, {%4,%5,%6,%7}, {%8,%9}, {%0,%1,%2,%3};"
        : "+f"(c[0]), "+f"(c[1]), "+f"(c[2]), "+f"(c[3])
        : "r"(a[0]), "r"(a[1]), "r"(a[2]), "r"(a[3]), "r"(b[0]), "r"(b[1]));
}

__global__ __launch_bounds__(256) void gemm_tc_kernel(
    const float* __restrict__ A, const float* __restrict__ B,
    const float* __restrict__ bias,
    const float* __restrict__ tscale, const float* __restrict__ tshift,
    float* __restrict__ C_, int M, int K, int N)
{
    __shared__ float As[GBK][GBM + 4];
    __shared__ float Bs[GBK][GBN + 4];
    int tid = threadIdx.x;
    int warp = tid >> 5, lane = tid & 31;
    int wm = warp & 3, wn = warp >> 2;
    int row0 = blockIdx.y * GBM;
    int col0 = blockIdx.x * GBN;
    int g = lane >> 2, t4 = lane & 3;

    float c[2][4][4];
    #pragma unroll
    for (int mm = 0; mm < 2; mm++)
        #pragma unroll
        for (int nn = 0; nn < 4; nn++)
            #pragma unroll
            for (int q = 0; q < 4; q++) c[mm][nn][q] = 0.f;

    for (int k0 = 0; k0 < K; k0 += GBK) {
        #pragma unroll
        for (int i = 0; i < 2; i++) {
            int idx = tid + 256 * i;
            int r = idx >> 2, c4 = idx & 3;
            int gr = row0 + r;
            float4 v = make_float4(0.f, 0.f, 0.f, 0.f);
            if (gr < M) v = *(const float4*)&A[(size_t)gr * K + k0 + c4 * 4];
            if (tscale) {
                int kb = k0 + c4 * 4;
                v.x = fmaxf(v.x * tscale[kb+0] + tshift[kb+0], 0.f);
                v.y = fmaxf(v.y * tscale[kb+1] + tshift[kb+1], 0.f);
                v.z = fmaxf(v.z * tscale[kb+2] + tshift[kb+2], 0.f);
                v.w = fmaxf(v.w * tscale[kb+3] + tshift[kb+3], 0.f);
            }
            As[c4*4+0][r] = v.x; As[c4*4+1][r] = v.y;
            As[c4*4+2][r] = v.z; As[c4*4+3][r] = v.w;
        }
        #pragma unroll
        for (int i = 0; i < 4; i++) {
            int idx = tid + 256 * i;
            int r = idx >> 6, cc = idx & 63;
            int gc = col0 + cc;
            float v = 0.f;
            if (gc < N) v = B[(size_t)(k0 + r) * N + gc];
            Bs[r][cc] = v;
        }
        __syncthreads();

        #pragma unroll
        for (int ks = 0; ks < GBK; ks += 8) {
            unsigned ahi[2][4], alo[2][4], bhi[4][2], blo[4][2];
            #pragma unroll
            for (int mm = 0; mm < 2; mm++) {
                int mrow = wm * 32 + mm * 16 + g;
                split_tf32(As[ks + t4][mrow],        ahi[mm][0], alo[mm][0]);
                split_tf32(As[ks + t4][mrow + 8],    ahi[mm][1], alo[mm][1]);
                split_tf32(As[ks + t4 + 4][mrow],    ahi[mm][2], alo[mm][2]);
                split_tf32(As[ks + t4 + 4][mrow + 8],ahi[mm][3], alo[mm][3]);
            }
            #pragma unroll
            for (int nn = 0; nn < 4; nn++) {
                int ncol = wn * 32 + nn * 8 + g;
                split_tf32(Bs[ks + t4][ncol],     bhi[nn][0], blo[nn][0]);
                split_tf32(Bs[ks + t4 + 4][ncol], bhi[nn][1], blo[nn][1]);
            }
            #pragma unroll
            for (int mm = 0; mm < 2; mm++)
                #pragma unroll
                for (int nn = 0; nn < 4; nn++) {
                    mma_tf32(c[mm][nn], ahi[mm], bhi[nn]);
                    mma_tf32(c[mm][nn], alo[mm], bhi[nn]);
                    mma_tf32(c[mm][nn], ahi[mm], blo[nn]);
                }
        }
        __syncthreads();
    }

    #pragma unroll
    for (int mm = 0; mm < 2; mm++) {
        int rbase = row0 + wm * 32 + mm * 16 + g;
        #pragma unroll
        for (int nn = 0; nn < 4; nn++) {
            int cbase = col0 + wn * 32 + nn * 8 + t4 * 2;
            #pragma unroll
            for (int q = 0; q < 4; q++) {
                int rr = rbase + ((q >= 2) ? 8 : 0);
                int cc = cbase + (q & 1);
                if (rr < M && cc < N) {
                    float v = c[mm][nn][q];
                    if (bias) v += bias[cc];
                    C_[(size_t)rr * N + cc] = v;
                }
            }
        }
    }
}

// ---------------- L1 fused single-pass GAT aggregation (wide h) ----------
template <int H, int C>
__global__ void gat_aggregate_kernel(const float* __restrict__ hx,
                                     const int* __restrict__ off,
                                     const int* __restrict__ csr_src,
                                     const float* __restrict__ bias,
                                     float* __restrict__ out, int M) {
    constexpr int HC = H * C;
    constexpr int NSTR = HC + 2 * H;
    constexpr int N2 = HC / 64;
    int warp = (blockIdx.x * blockDim.x + threadIdx.x) >> 5;
    int lane = threadIdx.x & 31;
    if (warp >= M) return;
    int i = warp;
    int beg = off[i], end = off[i + 1];

    float sd = (lane < H) ? hx[(size_t)i * NSTR + HC + H + lane] : 0.f;
    float z = 0.f;
    float2 acc[N2];
    int hd[N2];
    #pragma unroll
    for (int j = 0; j < N2; j++) {
        acc[j] = make_float2(0.f, 0.f);
        hd[j] = (2 * (lane + 32 * j)) / C;
    }

    for (int p = beg; p < end; p++) {
        int s = __ldg(&csr_src[p]);
        const float* row = hx + (size_t)s * NSTR;
        float ev = 0.f;
        if (lane < H) {
            float v = __ldg(&row[HC + lane]) + sd;
            v = (v > 0.f) ? v : NEG_SLOPE * v;
            ev = __expf(v);
            z += ev;
        }
        const float2* hrow = (const float2*)row;
        #pragma unroll
        for (int j = 0; j < N2; j++) {
            float a = __shfl_sync(0xffffffffu, ev, hd[j]);
            float2 hv = __ldg(&hrow[lane + 32 * j]);
            acc[j].x += a * hv.x;
            acc[j].y += a * hv.y;
        }
    }
    float zinv = (lane < H) ? 1.f / (z + 1e-16f) : 0.f;
    const float2* b2 = (const float2*)bias;
    float2* o2 = (float2*)(out + (size_t)i * HC);
    #pragma unroll
    for (int j = 0; j < N2; j++) {
        float zi = __shfl_sync(0xffffffffu, zinv, hd[j]);
        int idx = lane + 32 * j;
        float2 bb = b2[idx];
        o2[idx] = make_float2(acc[j].x * zi + bb.x, acc[j].y * zi + bb.y);
    }
}

// ---------------- L2/L3 input-side aggregation ---------------------------
// Aggregates BN+ReLU(xin) rows (DIN floats) weighted by per-head alpha into
// aggx[N, H*DIN]. sc rows: [s_src(H) | s_dst(H)], stride 2H.
// Requires H*DIN == 256.
template <int H, int DIN>
__global__ void gat_aggx_kernel(const float* __restrict__ xin,
                                const float* __restrict__ sc,
                                const float* __restrict__ bnscale,
                                const float* __restrict__ bnshift,
                                const int* __restrict__ off,
                                const int* __restrict__ csr_src,
                                float* __restrict__ aggx, int M) {
    constexpr int NACC = (H * DIN) / 32;   // 8
    int warp = (blockIdx.x * blockDim.x + threadIdx.x) >> 5;
    int lane = threadIdx.x & 31;
    if (warp >= M) return;
    int i = warp;
    int beg = off[i], end = off[i + 1];

    int k = lane & (DIN - 1);              // input-dim index for this lane
    float bsc = bnscale[k], bsh = bnshift[k];
    float sd = (lane < H) ? sc[(size_t)i * 2 * H + H + lane] : 0.f;

    float z = 0.f;
    float acc[NACC];
    int hd[NACC];
    #pragma unroll
    for (int j = 0; j < NACC; j++) {
        acc[j] = 0.f;
        hd[j] = (lane + 32 * j) / DIN;     // head index of acc element
    }

    for (int p = beg; p < end; p++) {
        int s = __ldg(&csr_src[p]);
        float ev = 0.f;
        if (lane < H) {
            float v = __ldg(&sc[(size_t)s * 2 * H + lane]) + sd;
            v = (v > 0.f) ? v : NEG_SLOPE * v;
            ev = __expf(v);
            z += ev;
        }
        float xv = fmaxf(__ldg(&xin[(size_t)s * DIN + k]) * bsc + bsh, 0.f);
        #pragma unroll
        for (int j = 0; j < NACC; j++) {
            float a = __shfl_sync(0xffffffffu, ev, hd[j]);
            acc[j] += a * xv;
        }
    }
    float zinv = (lane < H) ? 1.f / (z + 1e-16f) : 0.f;
    float* orow = aggx + (size_t)i * (H * DIN);
    #pragma unroll
    for (int j = 0; j < NACC; j++) {
        float zi = __shfl_sync(0xffffffffu, zinv, hd[j]);
        orow[lane + 32 * j] = acc[j] * zi;
    }
}

// ---------------- per-head linear: out[:,hC+c] = aggx[:,hDIN+k] W[k,hC+c] --
// W is the original [DIN, HC] matrix; head selection happens via aggx column.
template <int H, int DIN, int C, int NB>
__global__ void headlin_kernel(const float* __restrict__ aggx,
                               const float* __restrict__ W,
                               const float* __restrict__ bias,
                               float* __restrict__ out, int M) {
    constexpr int HC = H * C;
    constexpr int HD = H * DIN;
    extern __shared__ float smem[];
    float* Wsm = smem;                 // DIN*HC
    float* ax  = smem + DIN * HC;      // NB * HD
    int tid = threadIdx.x;             // HC threads
    int h = tid / C;

    for (int i = tid; i < DIN * HC; i += HC) Wsm[i] = W[i];

    int n0 = blockIdx.x * NB;
    // cooperative load of NB rows of aggx
    for (int i = tid; i < NB * HD; i += HC) {
        int r = i / HD, cc = i % HD;
        int n = n0 + r;
        ax[i] = (n < M) ? aggx[(size_t)n * HD + cc] : 0.f;
    }
    __syncthreads();

    float bb = bias[tid];
    #pragma unroll
    for (int r = 0; r < NB; r++) {
        int n = n0 + r;
        if (n >= M) break;
        float acc = 0.f;
        const float* axr = ax + r * HD + h * DIN;
        #pragma unroll
        for (int k = 0; k < DIN; k++)
            acc += Wsm[k * HC + tid] * axr[k];
        out[(size_t)n * HC + tid] = acc + bb;
    }
}

// ---------------- BatchNorm stats (atomic-free, 2-level) ----------------
__global__ void bn_stats_kernel(const float* __restrict__ X, int M, int D,
                                float* psum, float* psq) {
    int f = blockIdx.y * 128 + threadIdx.x;
    if (f >= D) return;
    int r0 = blockIdx.x * BN_ROWS;
    int rend = min(r0 + BN_ROWS, M);
    float s = 0.f, s2 = 0.f;
    for (int r = r0; r < rend; r++) {
        float v = X[(size_t)r * D + f];
        s += v; s2 += v * v;
    }
    psum[blockIdx.x * D + f] = s;
    psq [blockIdx.x * D + f] = s2;
}

__global__ void bn_finalize_kernel(const float* __restrict__ psum, const float* __restrict__ psq,
                                   const float* __restrict__ g, const float* __restrict__ be,
                                   float* scale, float* shift, int M, int D, int nchunks) {
    int f = blockIdx.x * blockDim.x + threadIdx.x;
    if (f >= D) return;
    float s = 0.f, s2 = 0.f;
    for (int c = 0; c < nchunks; c++) { s += psum[c * D + f]; s2 += psq[c * D + f]; }
    float inv = 1.f / (float)M;
    float mu = s * inv;
    float var = s2 * inv - mu * mu;
    float sc = g[f] * rsqrtf(var + EPS_BN);
    scale[f] = sc;
    shift[f] = be[f] - mu * sc;
}

// ---------------- pooling: segmented (batch sorted) + BN3+ReLU ----------
#define POOL_ROWS 512
__global__ void pool_bn_kernel(const float* __restrict__ h, const int* __restrict__ batch,
                               const float* __restrict__ scale, const float* __restrict__ shift,
                               float* pool, int* cnt, int M) {
    const int D = 384;
    int f = threadIdx.x;
    int r0 = blockIdx.x * POOL_ROWS;
    int rend = min(r0 + POOL_ROWS, M);
    float sc = scale[f], sh = shift[f];
    int cur = __ldg(&batch[r0]);
    float acc = 0.f;
    int count = 0;
    for (int r = r0; r < rend; r++) {
        int b = __ldg(&batch[r]);
        if (b != cur) {
            atomicAdd(&pool[cur * D + f], acc);
            if (f == 0) atomicAdd(&cnt[cur], count);
            acc = 0.f; count = 0; cur = b;
        }
        acc += fmaxf(h[(size_t)r * D + f] * sc + sh, 0.f);
        count++;
    }
    atomicAdd(&pool[cur * D + f], acc);
    if (f == 0) atomicAdd(&cnt[cur], count);
}

__global__ void pool_div_kernel(float* pooled, const float* pool, const int* cnt, int G, int D) {
    int t = blockIdx.x * blockDim.x + threadIdx.x;
    if (t >= G * D) return;
    int g = t / D;
    float c = fmaxf((float)cnt[g], 1.f);
    pooled[t] = pool[t] / c;
}

// ---------------- host-side orchestration ----------------
struct Ptrs {
    float *hx, *agg, *lin, *aggx, *bcat;
    int *deg, *off, *cursor, *csr, *partial;
    float *bnpsum, *bnpsq, *scale, *shift, *pool, *pooled;
    int *cnt;
};

static void launch_gemm(const float* A, const float* B, const float* bias,
                        const float* tscale, const float* tshift, float* C,
                        int M, int K, int N) {
    dim3 grid((N + GBN - 1) / GBN, (M + GBM - 1) / GBM);
    gemm_tc_kernel<<<grid, 256>>>(A, B, bias, tscale, tshift, C, M, K, N);
}

static void run_bn_stats(const float* X, int M, int D, const float* g, const float* be, Ptrs& P) {
    int nchunks = (M + BN_ROWS - 1) / BN_ROWS;
    dim3 sg(nchunks, (D + 127) / 128);
    bn_stats_kernel<<<sg, 128>>>(X, M, D, P.bnpsum, P.bnpsq);
    bn_finalize_kernel<<<(D + 127) / 128, 128>>>(P.bnpsum, P.bnpsq, g, be, P.scale, P.shift, M, D, nchunks);
}

extern "C" void kernel_launch(void* const* d_in, const int* in_sizes, int n_in,
                              void* d_out, int out_size) {
    const float* x     = (const float*)d_in[0];
    const int*   ei    = (const int*)  d_in[1];
    const int*   batch = (const int*)  d_in[2];
    const float* W1  = (const float*)d_in[3];
    const float* as1 = (const float*)d_in[4];
    const float* ad1 = (const float*)d_in[5];
    const float* b1  = (const float*)d_in[6];
    const float* g1  = (const float*)d_in[7];
    const float* be1 = (const float*)d_in[8];
    const float* lw1 = (const float*)d_in[9];
    const float* lb1 = (const float*)d_in[10];
    const float* gl1 = (const float*)d_in[11];
    const float* bel1= (const float*)d_in[12];
    const float* W2  = (const float*)d_in[13];
    const float* as2 = (const float*)d_in[14];
    const float* ad2 = (const float*)d_in[15];
    const float* b2  = (const float*)d_in[16];
    const float* g2  = (const float*)d_in[17];
    const float* be2 = (const float*)d_in[18];
    const float* lw2 = (const float*)d_in[19];
    const float* lb2 = (const float*)d_in[20];
    const float* gl2 = (const float*)d_in[21];
    const float* bel2= (const float*)d_in[22];
    const float* W3  = (const float*)d_in[23];
    const float* as3 = (const float*)d_in[24];
    const float* ad3 = (const float*)d_in[25];
    const float* b3  = (const float*)d_in[26];
    const float* g3  = (const float*)d_in[27];
    const float* be3 = (const float*)d_in[28];
    const float* lwf = (const float*)d_in[29];
    const float* lbf = (const float*)d_in[30];

    int M = in_sizes[2];
    int E = in_sizes[1] / 2;
    int EX = E + M;

    Ptrs P;
    cudaGetSymbolAddress((void**)&P.hx, d_hx);
    cudaGetSymbolAddress((void**)&P.agg, d_agg);
    cudaGetSymbolAddress((void**)&P.lin, d_lin);
    cudaGetSymbolAddress((void**)&P.aggx, d_aggx);
    cudaGetSymbolAddress((void**)&P.bcat, d_bcat);
    cudaGetSymbolAddress((void**)&P.deg, d_deg);
    cudaGetSymbolAddress((void**)&P.off, d_off);
    cudaGetSymbolAddress((void**)&P.cursor, d_cursor);
    cudaGetSymbolAddress((void**)&P.csr, d_csr);
    cudaGetSymbolAddress((void**)&P.partial, d_partial);
    cudaGetSymbolAddress((void**)&P.bnpsum, d_bnpsum);
    cudaGetSymbolAddress((void**)&P.bnpsq, d_bnpsq);
    cudaGetSymbolAddress((void**)&P.scale, d_scale);
    cudaGetSymbolAddress((void**)&P.shift, d_shift);
    cudaGetSymbolAddress((void**)&P.pool, d_pool);
    cudaGetSymbolAddress((void**)&P.pooled, d_pooled);
    cudaGetSymbolAddress((void**)&P.cnt, d_cnt);

    // opt-in smem for the layer-3 head-linear (52KB)
    cudaFuncSetAttribute(headlin_kernel<8, 32, 48, 4>,
                         cudaFuncAttributeMaxDynamicSharedMemorySize, 56 * 1024);
    cudaFuncSetAttribute(headlin_kernel<16, 16, 32, 4>,
                         cudaFuncAttributeMaxDynamicSharedMemorySize, 56 * 1024);

    // ---- CSR build ----
    zero_i_kernel<<<(M + 255) / 256, 256>>>(P.deg, M);
    edge_hist_kernel<<<(EX + 255) / 256, 256>>>(ei, E, M, P.deg);
    int nb = (M + 1023) / 1024;
    scan_block_kernel<<<nb, 1024>>>(P.deg, P.off, P.partial, M);
    scan_add_kernel<<<(M + 255) / 256, 256>>>(P.off, P.partial, P.cursor, M, EX);
    edge_scatter_kernel<<<(EX + 255) / 256, 256>>>(ei, E, M, P.cursor, P.csr);

    const int wpb = 8;
    int ablk = (M + wpb - 1) / wpb;

    // ---- Layer 1: GAT(128 -> 20x16=320), NC=360 (wide path) ----
    build_bcat_kernel<<<(128 * 360 + 255) / 256, 256>>>(W1, as1, ad1, P.bcat, 128, 20, 16);
    launch_gemm(x, P.bcat, nullptr, nullptr, nullptr, P.hx, M, 128, 360);
    gat_aggregate_kernel<20, 16><<<ablk, wpb * 32>>>(P.hx, P.off, P.csr, b1, P.agg, M);
    run_bn_stats(P.agg, M, 320, g1, be1, P);
    launch_gemm(P.agg, lw1, lb1, P.scale, P.shift, P.lin, M, 320, 16);
    run_bn_stats(P.lin, M, 16, gl1, bel1, P);

    // ---- Layer 2: GAT(16 -> 16x32=512) via input-side aggregation ----
    // scores: [N,16] @ [16,32]
    build_bsc_kernel<<<(16 * 32 + 255) / 256, 256>>>(W2, as2, ad2, P.bcat, 16, 16, 32);
    launch_gemm(P.lin, P.bcat, nullptr, P.scale, P.shift, P.hx, M, 16, 32);
    gat_aggx_kernel<16, 16><<<ablk, wpb * 32>>>(P.lin, P.hx, P.scale, P.shift, P.off, P.csr, P.aggx, M);
    {
        int smem = (16 * 512 + 4 * 256) * 4;
        headlin_kernel<16, 16, 32, 4><<<(M + 3) / 4, 512, smem>>>(P.aggx, W2, b2, P.agg, M);
    }
    run_bn_stats(P.agg, M, 512, g2, be2, P);
    launch_gemm(P.agg, lw2, lb2, P.scale, P.shift, P.lin, M, 512, 32);
    run_bn_stats(P.lin, M, 32, gl2, bel2, P);

    // ---- Layer 3: GAT(32 -> 8x48=384) via input-side aggregation ----
    build_bsc_kernel<<<(32 * 16 + 255) / 256, 256>>>(W3, as3, ad3, P.bcat, 32, 8, 48);
    launch_gemm(P.lin, P.bcat, nullptr, P.scale, P.shift, P.hx, M, 32, 16);
    gat_aggx_kernel<8, 32><<<ablk, wpb * 32>>>(P.lin, P.hx, P.scale, P.shift, P.off, P.csr, P.aggx, M);
    {
        int smem = (32 * 384 + 4 * 256) * 4;
        headlin_kernel<8, 32, 48, 4><<<(M + 3) / 4, 384, smem>>>(P.aggx, W3, b3, P.agg, M);
    }
    run_bn_stats(P.agg, M, 384, g3, be3, P);

    // ---- global mean pool (fused BN3+ReLU, segmented) + final linear ----
    zero_pool_kernel<<<(GG * 384 + 255) / 256, 256>>>(P.pool, P.cnt);
    pool_bn_kernel<<<(M + POOL_ROWS - 1) / POOL_ROWS, 384>>>(P.agg, batch, P.scale, P.shift, P.pool, P.cnt, M);
    pool_div_kernel<<<(GG * 384 + 255) / 256, 256>>>(P.pooled, P.pool, P.cnt, GG, 384);
    launch_gemm(P.pooled, lwf, lbf, nullptr, nullptr, (float*)d_out, GG, 384, 10);
}

// round 10
// speedup vs baseline: 1.8666x; 1.1294x over previous
#include <cuda_runtime.h>
#include <cuda_bf16.h>
#include <math.h>

// ---------------- problem constants ----------------
#define NN   50000
#define EEX  450000
#define GG   64
#define DMAX 544
#define EPS_BN 1e-5f
#define NEG_SLOPE 0.2f

// ---------------- static scratch ----------------
__device__ float d_hx [(size_t)NN * DMAX];   // L1: [h|s_src|s_dst]; L2/3: scores
__device__ float d_agg[(size_t)NN * 512];
__device__ float d_lin[(size_t)NN * 64];
__device__ float d_aggx[(size_t)NN * 256];
__device__ float d_bcat[128 * DMAX];
__device__ int   d_deg[NN];
__device__ int   d_off[NN + 1];
__device__ int   d_cursor[NN];
__device__ int   d_csr[EEX];
__device__ int   d_partial[128];
__device__ float d_bnsum[512];
__device__ float d_bnsq [512];
__device__ float d_scale[512];
__device__ float d_shift[512];
__device__ float d_pool[GG * 384];
__device__ int   d_cnt [GG];
__device__ float d_pooled[GG * 384];

// ---------------- small utility kernels ----------------
__global__ void zero_i_kernel(int* p, int n) {
    int t = blockIdx.x * blockDim.x + threadIdx.x;
    if (t < n) p[t] = 0;
}
__global__ void zero_stats_kernel(float* s, float* q) {
    int t = threadIdx.x;
    if (t < 512) { s[t] = 0.f; q[t] = 0.f; }
}
__global__ void zero_pool_kernel(float* pool, int* cnt) {
    int t = blockIdx.x * blockDim.x + threadIdx.x;
    if (t < GG * 384) pool[t] = 0.f;
    if (t < GG) cnt[t] = 0;
}

// ---------------- CSR build ----------------
__global__ void edge_hist_kernel(const int* __restrict__ ei, int E, int n, int* deg) {
    int t = blockIdx.x * blockDim.x + threadIdx.x;
    int total = E + n;
    if (t >= total) return;
    int dst = (t < E) ? ei[E + t] : (t - E);
    atomicAdd(&deg[dst], 1);
}

__global__ void scan_block_kernel(const int* __restrict__ deg, int* off, int* partial, int n) {
    __shared__ int sm[1024];
    int gid = blockIdx.x * 1024 + threadIdx.x;
    int v = (gid < n) ? deg[gid] : 0;
    sm[threadIdx.x] = v;
    __syncthreads();
    for (int d = 1; d < 1024; d <<= 1) {
        int t = (threadIdx.x >= d) ? sm[threadIdx.x - d] : 0;
        __syncthreads();
        sm[threadIdx.x] += t;
        __syncthreads();
    }
    if (gid < n) off[gid] = sm[threadIdx.x] - v;
    if (threadIdx.x == 1023) partial[blockIdx.x] = sm[1023];
}

__global__ void scan_add_kernel(int* off, const int* __restrict__ partial, int* cursor,
                                int n, int total) {
    int gid = blockIdx.x * blockDim.x + threadIdx.x;
    if (gid < n) {
        int pb = gid >> 10;
        int base = 0;
        for (int j = 0; j < pb; j++) base += partial[j];
        int v = off[gid] + base;
        off[gid] = v;
        cursor[gid] = v;
    }
    if (gid == 0) off[n] = total;
}

__global__ void edge_scatter_kernel(const int* __restrict__ ei, int E, int n,
                                    int* cursor, int* csr_src) {
    int t = blockIdx.x * blockDim.x + threadIdx.x;
    int total = E + n;
    if (t >= total) return;
    int src, dst;
    if (t < E) { src = ei[t]; dst = ei[E + t]; }
    else       { src = t - E; dst = t - E; }
    int pos = atomicAdd(&cursor[dst], 1);
    csr_src[pos] = src;
}

// ---------------- weight preprocessing ----------------
__global__ void build_bcat_kernel(const float* __restrict__ W,
                                  const float* __restrict__ a_s,
                                  const float* __restrict__ a_d,
                                  float* __restrict__ bcat, int K, int H, int C) {
    int HC = H * C;
    int NC = HC + 2 * H;
    int idx = blockIdx.x * blockDim.x + threadIdx.x;
    if (idx >= K * NC) return;
    int k = idx / NC, col = idx % NC;
    if (col < HC) {
        bcat[idx] = W[(size_t)k * HC + col];
    } else {
        int hh = col - HC;
        const float* a = (hh >= H) ? a_d : a_s;
        if (hh >= H) hh -= H;
        float s = 0.f;
        for (int c = 0; c < C; c++) s += W[(size_t)k * HC + hh * C + c] * a[hh * C + c];
        bcat[idx] = s;
    }
}

__global__ void build_bsc_kernel(const float* __restrict__ W,
                                 const float* __restrict__ a_s,
                                 const float* __restrict__ a_d,
                                 float* __restrict__ bsc, int K, int H, int C) {
    int HC = H * C;
    int NC = 2 * H;
    int idx = blockIdx.x * blockDim.x + threadIdx.x;
    if (idx >= K * NC) return;
    int k = idx / NC, col = idx % NC;
    int hh = (col >= H) ? col - H : col;
    const float* a = (col >= H) ? a_d : a_s;
    float s = 0.f;
    for (int c = 0; c < C; c++) s += W[(size_t)k * HC + hh * C + c] * a[hh * C + c];
    bsc[idx] = s;
}

// ---------------- tensor-core GEMM (3xTF32, pre-split smem) ----------------
#define GBM 128
#define GBN 64
#define GBK 16

__device__ __forceinline__ void split_tf32(float x, unsigned& hi, unsigned& lo) {
    unsigned h_;
    asm("cvt.rna.tf32.f32 %0, %1;" : "=r"(h_) : "f"(x));
    float lf = x - __uint_as_float(h_);
    unsigned l_;
    asm("cvt.rna.tf32.f32 %0, %1;" : "=r"(l_) : "f"(lf));
    hi = h_; lo = l_;
}

__device__ __forceinline__ void mma_tf32(float c[4], const unsigned a[4], const unsigned b[2]) {
    asm volatile(
        "mma.sync.aligned.m16n8k8.row.col.f32.tf32.tf32.f32 "
        "{%0,%1,%2,%3}, {%4,%5,%6,%7}, {%8,%9}, {%0,%1,%2,%3};"
        : "+f"(c[0]), "+f"(c[1]), "+f"(c[2]), "+f"(c[3])
        : "r"(a[0]), "r"(a[1]), "r"(a[2]), "r"(a[3]), "r"(b[0]), "r"(b[1]));
}

__global__ __launch_bounds__(256) void gemm_tc_kernel(
    const float* __restrict__ A, const float* __restrict__ B,
    const float* __restrict__ bias,
    const float* __restrict__ tscale, const float* __restrict__ tshift,
    float* __restrict__ C_, float* ssum, float* ssq, int M, int K, int N)
{
    __shared__ unsigned AsH[GBK][GBM + 4];
    __shared__ unsigned AsL[GBK][GBM + 4];
    __shared__ unsigned BsH[GBK][GBN + 4];
    __shared__ unsigned BsL[GBK][GBN + 4];
    __shared__ float redS[GBN], redQ[GBN];
    int tid = threadIdx.x;
    int warp = tid >> 5, lane = tid & 31;
    int wm = warp & 3, wn = warp >> 2;
    int row0 = blockIdx.y * GBM;
    int col0 = blockIdx.x * GBN;
    int g = lane >> 2, t4 = lane & 3;

    float c[2][4][4];
    #pragma unroll
    for (int mm = 0; mm < 2; mm++)
        #pragma unroll
        for (int nn = 0; nn < 4; nn++)
            #pragma unroll
            for (int q = 0; q < 4; q++) c[mm][nn][q] = 0.f;

    for (int k0 = 0; k0 < K; k0 += GBK) {
        #pragma unroll
        for (int i = 0; i < 2; i++) {
            int idx = tid + 256 * i;
            int r = idx >> 2, c4 = idx & 3;
            int gr = row0 + r;
            float4 v = make_float4(0.f, 0.f, 0.f, 0.f);
            if (gr < M) v = *(const float4*)&A[(size_t)gr * K + k0 + c4 * 4];
            if (tscale) {
                int kb = k0 + c4 * 4;
                v.x = fmaxf(v.x * tscale[kb+0] + tshift[kb+0], 0.f);
                v.y = fmaxf(v.y * tscale[kb+1] + tshift[kb+1], 0.f);
                v.z = fmaxf(v.z * tscale[kb+2] + tshift[kb+2], 0.f);
                v.w = fmaxf(v.w * tscale[kb+3] + tshift[kb+3], 0.f);
            }
            unsigned hi, lo;
            split_tf32(v.x, hi, lo); AsH[c4*4+0][r] = hi; AsL[c4*4+0][r] = lo;
            split_tf32(v.y, hi, lo); AsH[c4*4+1][r] = hi; AsL[c4*4+1][r] = lo;
            split_tf32(v.z, hi, lo); AsH[c4*4+2][r] = hi; AsL[c4*4+2][r] = lo;
            split_tf32(v.w, hi, lo); AsH[c4*4+3][r] = hi; AsL[c4*4+3][r] = lo;
        }
        #pragma unroll
        for (int i = 0; i < 4; i++) {
            int idx = tid + 256 * i;
            int r = idx >> 6, cc = idx & 63;
            int gc = col0 + cc;
            float v = 0.f;
            if (gc < N) v = B[(size_t)(k0 + r) * N + gc];
            unsigned hi, lo;
            split_tf32(v, hi, lo);
            BsH[r][cc] = hi; BsL[r][cc] = lo;
        }
        __syncthreads();

        #pragma unroll
        for (int ks = 0; ks < GBK; ks += 8) {
            unsigned ahi[2][4], alo[2][4], bhi[4][2], blo[4][2];
            #pragma unroll
            for (int mm = 0; mm < 2; mm++) {
                int mrow = wm * 32 + mm * 16 + g;
                ahi[mm][0] = AsH[ks + t4][mrow];      alo[mm][0] = AsL[ks + t4][mrow];
                ahi[mm][1] = AsH[ks + t4][mrow + 8];  alo[mm][1] = AsL[ks + t4][mrow + 8];
                ahi[mm][2] = AsH[ks + t4 + 4][mrow];  alo[mm][2] = AsL[ks + t4 + 4][mrow];
                ahi[mm][3] = AsH[ks + t4 + 4][mrow+8];alo[mm][3] = AsL[ks + t4 + 4][mrow+8];
            }
            #pragma unroll
            for (int nn = 0; nn < 4; nn++) {
                int ncol = wn * 32 + nn * 8 + g;
                bhi[nn][0] = BsH[ks + t4][ncol];      blo[nn][0] = BsL[ks + t4][ncol];
                bhi[nn][1] = BsH[ks + t4 + 4][ncol];  blo[nn][1] = BsL[ks + t4 + 4][ncol];
            }
            #pragma unroll
            for (int mm = 0; mm < 2; mm++)
                #pragma unroll
                for (int nn = 0; nn < 4; nn++) {
                    mma_tf32(c[mm][nn], ahi[mm], bhi[nn]);
                    mma_tf32(c[mm][nn], alo[mm], bhi[nn]);
                    mma_tf32(c[mm][nn], ahi[mm], blo[nn]);
                }
        }
        __syncthreads();
    }

    // add bias into accumulators, then store
    #pragma unroll
    for (int mm = 0; mm < 2; mm++) {
        int rbase = row0 + wm * 32 + mm * 16 + g;
        #pragma unroll
        for (int nn = 0; nn < 4; nn++) {
            int cbase = col0 + wn * 32 + nn * 8 + t4 * 2;
            #pragma unroll
            for (int q = 0; q < 4; q++) {
                int rr = rbase + ((q >= 2) ? 8 : 0);
                int cc = cbase + (q & 1);
                if (rr < M && cc < N) {
                    float v = c[mm][nn][q];
                    if (bias) v += bias[cc];
                    c[mm][nn][q] = v;
                    C_[(size_t)rr * N + cc] = v;
                }
            }
        }
    }

    // fused BN stats over output columns
    if (ssum) {
        if (tid < GBN) { redS[tid] = 0.f; redQ[tid] = 0.f; }
        __syncthreads();
        #pragma unroll
        for (int nn = 0; nn < 4; nn++) {
            #pragma unroll
            for (int par = 0; par < 2; par++) {
                int lcol = wn * 32 + nn * 8 + t4 * 2 + par;
                int cc = col0 + lcol;
                if (cc >= N) continue;
                float s = 0.f, q2 = 0.f;
                #pragma unroll
                for (int mm = 0; mm < 2; mm++) {
                    #pragma unroll
                    for (int rh = 0; rh < 2; rh++) {
                        int rr = row0 + wm * 32 + mm * 16 + g + rh * 8;
                        if (rr < M) {
                            float v = c[mm][nn][par + 2 * rh];
                            s += v; q2 += v * v;
                        }
                    }
                }
                atomicAdd(&redS[lcol], s);
                atomicAdd(&redQ[lcol], q2);
            }
        }
        __syncthreads();
        if (tid < GBN && col0 + tid < N) {
            atomicAdd(&ssum[col0 + tid], redS[tid]);
            atomicAdd(&ssq [col0 + tid], redQ[tid]);
        }
    }
}

// ---------------- L1 fused single-pass GAT aggregation + BN stats --------
template <int H, int C>
__global__ void gat_aggregate_kernel(const float* __restrict__ hx,
                                     const int* __restrict__ off,
                                     const int* __restrict__ csr_src,
                                     const float* __restrict__ bias,
                                     float* __restrict__ out,
                                     float* ssum, float* ssq, int M) {
    constexpr int HC = H * C;
    constexpr int NSTR = HC + 2 * H;
    constexpr int N2 = HC / 64;
    __shared__ float sS[HC], sQ[HC];
    int tid = threadIdx.x;
    for (int i = tid; i < HC; i += blockDim.x) { sS[i] = 0.f; sQ[i] = 0.f; }
    __syncthreads();

    int warp = (blockIdx.x * blockDim.x + tid) >> 5;
    int lane = tid & 31;
    bool valid = (warp < M);
    int i = valid ? warp : 0;
    int beg = off[i], end = off[i + 1];

    float sd = (lane < H) ? hx[(size_t)i * NSTR + HC + H + lane] : 0.f;
    float z = 0.f;
    float2 acc[N2];
    int hd[N2];
    #pragma unroll
    for (int j = 0; j < N2; j++) {
        acc[j] = make_float2(0.f, 0.f);
        hd[j] = (2 * (lane + 32 * j)) / C;
    }

    if (valid) {
        for (int p = beg; p < end; p++) {
            int s = __ldg(&csr_src[p]);
            const float* row = hx + (size_t)s * NSTR;
            float ev = 0.f;
            if (lane < H) {
                float v = __ldg(&row[HC + lane]) + sd;
                v = (v > 0.f) ? v : NEG_SLOPE * v;
                ev = __expf(v);
                z += ev;
            }
            const float2* hrow = (const float2*)row;
            #pragma unroll
            for (int j = 0; j < N2; j++) {
                float a = __shfl_sync(0xffffffffu, ev, hd[j]);
                float2 hv = __ldg(&hrow[lane + 32 * j]);
                acc[j].x += a * hv.x;
                acc[j].y += a * hv.y;
            }
        }
        float zinv = (lane < H) ? 1.f / (z + 1e-16f) : 0.f;
        const float2* b2 = (const float2*)bias;
        float2* o2 = (float2*)(out + (size_t)i * HC);
        #pragma unroll
        for (int j = 0; j < N2; j++) {
            float zi = __shfl_sync(0xffffffffu, zinv, hd[j]);
            int idx = lane + 32 * j;
            float2 bb = b2[idx];
            float ox = acc[j].x * zi + bb.x;
            float oy = acc[j].y * zi + bb.y;
            o2[idx] = make_float2(ox, oy);
            atomicAdd(&sS[2*idx],   ox);
            atomicAdd(&sS[2*idx+1], oy);
            atomicAdd(&sQ[2*idx],   ox*ox);
            atomicAdd(&sQ[2*idx+1], oy*oy);
        }
    }
    __syncthreads();
    for (int f = tid; f < HC; f += blockDim.x) {
        atomicAdd(&ssum[f], sS[f]);
        atomicAdd(&ssq [f], sQ[f]);
    }
}

// ---------------- L2/L3 input-side aggregation ---------------------------
template <int H, int DIN>
__global__ void gat_aggx_kernel(const float* __restrict__ xin,
                                const float* __restrict__ sc,
                                const float* __restrict__ bnscale,
                                const float* __restrict__ bnshift,
                                const int* __restrict__ off,
                                const int* __restrict__ csr_src,
                                float* __restrict__ aggx, int M) {
    constexpr int NACC = (H * DIN) / 32;
    int warp = (blockIdx.x * blockDim.x + threadIdx.x) >> 5;
    int lane = threadIdx.x & 31;
    if (warp >= M) return;
    int i = warp;
    int beg = off[i], end = off[i + 1];

    int k = lane & (DIN - 1);
    float bsc = bnscale[k], bsh = bnshift[k];
    float sd = (lane < H) ? sc[(size_t)i * 2 * H + H + lane] : 0.f;

    float z = 0.f;
    float acc[NACC];
    int hd[NACC];
    #pragma unroll
    for (int j = 0; j < NACC; j++) {
        acc[j] = 0.f;
        hd[j] = (lane + 32 * j) / DIN;
    }

    for (int p = beg; p < end; p++) {
        int s = __ldg(&csr_src[p]);
        float ev = 0.f;
        if (lane < H) {
            float v = __ldg(&sc[(size_t)s * 2 * H + lane]) + sd;
            v = (v > 0.f) ? v : NEG_SLOPE * v;
            ev = __expf(v);
            z += ev;
        }
        float xv = fmaxf(__ldg(&xin[(size_t)s * DIN + k]) * bsc + bsh, 0.f);
        #pragma unroll
        for (int j = 0; j < NACC; j++) {
            float a = __shfl_sync(0xffffffffu, ev, hd[j]);
            acc[j] += a * xv;
        }
    }
    float zinv = (lane < H) ? 1.f / (z + 1e-16f) : 0.f;
    float* orow = aggx + (size_t)i * (H * DIN);
    #pragma unroll
    for (int j = 0; j < NACC; j++) {
        float zi = __shfl_sync(0xffffffffu, zinv, hd[j]);
        orow[lane + 32 * j] = acc[j] * zi;
    }
}

// ---------------- per-head linear + fused BN stats ----------------------
template <int H, int DIN, int C, int NB>
__global__ void headlin_kernel(const float* __restrict__ aggx,
                               const float* __restrict__ W,
                               const float* __restrict__ bias,
                               float* __restrict__ out,
                               float* ssum, float* ssq, int M) {
    constexpr int HC = H * C;
    constexpr int HD = H * DIN;
    extern __shared__ float smem[];
    float* Wsm = smem;
    float* ax  = smem + DIN * HC;
    int tid = threadIdx.x;             // HC threads
    int h = tid / C;

    for (int i = tid; i < DIN * HC; i += HC) Wsm[i] = W[i];

    int n0 = blockIdx.x * NB;
    for (int i = tid; i < NB * HD; i += HC) {
        int r = i / HD, cc = i % HD;
        int n = n0 + r;
        ax[i] = (n < M) ? aggx[(size_t)n * HD + cc] : 0.f;
    }
    __syncthreads();

    float bb = bias[tid];
    float s = 0.f, q2 = 0.f;
    #pragma unroll
    for (int r = 0; r < NB; r++) {
        int n = n0 + r;
        if (n >= M) break;
        float acc = 0.f;
        const float* axr = ax + r * HD + h * DIN;
        #pragma unroll
        for (int k = 0; k < DIN; k++)
            acc += Wsm[k * HC + tid] * axr[k];
        float v = acc + bb;
        out[(size_t)n * HC + tid] = v;
        s += v; q2 += v * v;
    }
    atomicAdd(&ssum[tid], s);
    atomicAdd(&ssq [tid], q2);
}

// ---------------- BN finalize (reads + zeroes accumulators) --------------
__global__ void bn_finalize_kernel(float* ssum, float* ssq,
                                   const float* __restrict__ g, const float* __restrict__ be,
                                   float* scale, float* shift, int M, int D) {
    int f = blockIdx.x * blockDim.x + threadIdx.x;
    if (f >= D) return;
    float inv = 1.f / (float)M;
    float mu = ssum[f] * inv;
    float var = ssq[f] * inv - mu * mu;
    float sc = g[f] * rsqrtf(var + EPS_BN);
    scale[f] = sc;
    shift[f] = be[f] - mu * sc;
    ssum[f] = 0.f;
    ssq [f] = 0.f;
}

// ---------------- pooling: segmented + BN3+ReLU ----------
#define POOL_ROWS 128
__global__ void pool_bn_kernel(const float* __restrict__ h, const int* __restrict__ batch,
                               const float* __restrict__ scale, const float* __restrict__ shift,
                               float* pool, int* cnt, int M) {
    const int D = 384;
    int f = threadIdx.x;
    int r0 = blockIdx.x * POOL_ROWS;
    int rend = min(r0 + POOL_ROWS, M);
    float sc = scale[f], sh = shift[f];
    int cur = __ldg(&batch[r0]);
    float acc = 0.f;
    int count = 0;
    for (int r = r0; r < rend; r++) {
        int b = __ldg(&batch[r]);
        if (b != cur) {
            atomicAdd(&pool[cur * D + f], acc);
            if (f == 0) atomicAdd(&cnt[cur], count);
            acc = 0.f; count = 0; cur = b;
        }
        acc += fmaxf(h[(size_t)r * D + f] * sc + sh, 0.f);
        count++;
    }
    atomicAdd(&pool[cur * D + f], acc);
    if (f == 0) atomicAdd(&cnt[cur], count);
}

__global__ void pool_div_kernel(float* pooled, const float* pool, const int* cnt, int G, int D) {
    int t = blockIdx.x * blockDim.x + threadIdx.x;
    if (t >= G * D) return;
    int g = t / D;
    float c = fmaxf((float)cnt[g], 1.f);
    pooled[t] = pool[t] / c;
}

// ---------------- host-side orchestration ----------------
struct Ptrs {
    float *hx, *agg, *lin, *aggx, *bcat;
    int *deg, *off, *cursor, *csr, *partial;
    float *bnsum, *bnsq, *scale, *shift, *pool, *pooled;
    int *cnt;
};

static void launch_gemm(const float* A, const float* B, const float* bias,
                        const float* tscale, const float* tshift, float* C,
                        float* ssum, float* ssq, int M, int K, int N) {
    dim3 grid((N + GBN - 1) / GBN, (M + GBM - 1) / GBM);
    gemm_tc_kernel<<<grid, 256>>>(A, B, bias, tscale, tshift, C, ssum, ssq, M, K, N);
}

extern "C" void kernel_launch(void* const* d_in, const int* in_sizes, int n_in,
                              void* d_out, int out_size) {
    const float* x     = (const float*)d_in[0];
    const int*   ei    = (const int*)  d_in[1];
    const int*   batch = (const int*)  d_in[2];
    const float* W1  = (const float*)d_in[3];
    const float* as1 = (const float*)d_in[4];
    const float* ad1 = (const float*)d_in[5];
    const float* b1  = (const float*)d_in[6];
    const float* g1  = (const float*)d_in[7];
    const float* be1 = (const float*)d_in[8];
    const float* lw1 = (const float*)d_in[9];
    const float* lb1 = (const float*)d_in[10];
    const float* gl1 = (const float*)d_in[11];
    const float* bel1= (const float*)d_in[12];
    const float* W2  = (const float*)d_in[13];
    const float* as2 = (const float*)d_in[14];
    const float* ad2 = (const float*)d_in[15];
    const float* b2  = (const float*)d_in[16];
    const float* g2  = (const float*)d_in[17];
    const float* be2 = (const float*)d_in[18];
    const float* lw2 = (const float*)d_in[19];
    const float* lb2 = (const float*)d_in[20];
    const float* gl2 = (const float*)d_in[21];
    const float* bel2= (const float*)d_in[22];
    const float* W3  = (const float*)d_in[23];
    const float* as3 = (const float*)d_in[24];
    const float* ad3 = (const float*)d_in[25];
    const float* b3  = (const float*)d_in[26];
    const float* g3  = (const float*)d_in[27];
    const float* be3 = (const float*)d_in[28];
    const float* lwf = (const float*)d_in[29];
    const float* lbf = (const float*)d_in[30];

    int M = in_sizes[2];
    int E = in_sizes[1] / 2;
    int EX = E + M;

    Ptrs P;
    cudaGetSymbolAddress((void**)&P.hx, d_hx);
    cudaGetSymbolAddress((void**)&P.agg, d_agg);
    cudaGetSymbolAddress((void**)&P.lin, d_lin);
    cudaGetSymbolAddress((void**)&P.aggx, d_aggx);
    cudaGetSymbolAddress((void**)&P.bcat, d_bcat);
    cudaGetSymbolAddress((void**)&P.deg, d_deg);
    cudaGetSymbolAddress((void**)&P.off, d_off);
    cudaGetSymbolAddress((void**)&P.cursor, d_cursor);
    cudaGetSymbolAddress((void**)&P.csr, d_csr);
    cudaGetSymbolAddress((void**)&P.partial, d_partial);
    cudaGetSymbolAddress((void**)&P.bnsum, d_bnsum);
    cudaGetSymbolAddress((void**)&P.bnsq, d_bnsq);
    cudaGetSymbolAddress((void**)&P.scale, d_scale);
    cudaGetSymbolAddress((void**)&P.shift, d_shift);
    cudaGetSymbolAddress((void**)&P.pool, d_pool);
    cudaGetSymbolAddress((void**)&P.pooled, d_pooled);
    cudaGetSymbolAddress((void**)&P.cnt, d_cnt);

    cudaFuncSetAttribute(headlin_kernel<8, 32, 48, 4>,
                         cudaFuncAttributeMaxDynamicSharedMemorySize, 56 * 1024);
    cudaFuncSetAttribute(headlin_kernel<16, 16, 32, 4>,
                         cudaFuncAttributeMaxDynamicSharedMemorySize, 56 * 1024);

    // ---- init + CSR build ----
    zero_stats_kernel<<<1, 512>>>(P.bnsum, P.bnsq);
    zero_i_kernel<<<(M + 255) / 256, 256>>>(P.deg, M);
    edge_hist_kernel<<<(EX + 255) / 256, 256>>>(ei, E, M, P.deg);
    int nb = (M + 1023) / 1024;
    scan_block_kernel<<<nb, 1024>>>(P.deg, P.off, P.partial, M);
    scan_add_kernel<<<(M + 255) / 256, 256>>>(P.off, P.partial, P.cursor, M, EX);
    edge_scatter_kernel<<<(EX + 255) / 256, 256>>>(ei, E, M, P.cursor, P.csr);

    const int wpb = 8;
    int ablk = (M + wpb - 1) / wpb;

    // ---- Layer 1: GAT(128 -> 20x16=320), NC=360 ----
    build_bcat_kernel<<<(128 * 360 + 255) / 256, 256>>>(W1, as1, ad1, P.bcat, 128, 20, 16);
    launch_gemm(x, P.bcat, nullptr, nullptr, nullptr, P.hx, nullptr, nullptr, M, 128, 360);
    gat_aggregate_kernel<20, 16><<<ablk, wpb * 32>>>(P.hx, P.off, P.csr, b1, P.agg, P.bnsum, P.bnsq, M);
    bn_finalize_kernel<<<3, 128>>>(P.bnsum, P.bnsq, g1, be1, P.scale, P.shift, M, 320);
    launch_gemm(P.agg, lw1, lb1, P.scale, P.shift, P.lin, P.bnsum, P.bnsq, M, 320, 16);
    bn_finalize_kernel<<<1, 128>>>(P.bnsum, P.bnsq, gl1, bel1, P.scale, P.shift, M, 16);

    // ---- Layer 2: GAT(16 -> 16x32=512) via input-side aggregation ----
    build_bsc_kernel<<<(16 * 32 + 255) / 256, 256>>>(W2, as2, ad2, P.bcat, 16, 16, 32);
    launch_gemm(P.lin, P.bcat, nullptr, P.scale, P.shift, P.hx, nullptr, nullptr, M, 16, 32);
    gat_aggx_kernel<16, 16><<<ablk, wpb * 32>>>(P.lin, P.hx, P.scale, P.shift, P.off, P.csr, P.aggx, M);
    {
        int smem = (16 * 512 + 4 * 256) * 4;
        headlin_kernel<16, 16, 32, 4><<<(M + 3) / 4, 512, smem>>>(P.aggx, W2, b2, P.agg, P.bnsum, P.bnsq, M);
    }
    bn_finalize_kernel<<<4, 128>>>(P.bnsum, P.bnsq, g2, be2, P.scale, P.shift, M, 512);
    launch_gemm(P.agg, lw2, lb2, P.scale, P.shift, P.lin, P.bnsum, P.bnsq, M, 512, 32);
    bn_finalize_kernel<<<1, 128>>>(P.bnsum, P.bnsq, gl2, bel2, P.scale, P.shift, M, 32);

    // ---- Layer 3: GAT(32 -> 8x48=384) via input-side aggregation ----
    build_bsc_kernel<<<(32 * 16 + 255) / 256, 256>>>(W3, as3, ad3, P.bcat, 32, 8, 48);
    launch_gemm(P.lin, P.bcat, nullptr, P.scale, P.shift, P.hx, nullptr, nullptr, M, 32, 16);
    gat_aggx_kernel<8, 32><<<ablk, wpb * 32>>>(P.lin, P.hx, P.scale, P.shift, P.off, P.csr, P.aggx, M);
    {
        int smem = (32 * 384 + 4 * 256) * 4;
        headlin_kernel<8, 32, 48, 4><<<(M + 3) / 4, 384, smem>>>(P.aggx, W3, b3, P.agg, P.bnsum, P.bnsq, M);
    }
    bn_finalize_kernel<<<3, 128>>>(P.bnsum, P.bnsq, g3, be3, P.scale, P.shift, M, 384);

    // ---- global mean pool (fused BN3+ReLU, segmented) + final linear ----
    zero_pool_kernel<<<(GG * 384 + 255) / 256, 256>>>(P.pool, P.cnt);
    pool_bn_kernel<<<(M + POOL_ROWS - 1) / POOL_ROWS, 384>>>(P.agg, batch, P.scale, P.shift, P.pool, P.cnt, M);
    pool_div_kernel<<<(GG * 384 + 255) / 256, 256>>>(P.pooled, P.pool, P.cnt, GG, 384);
    launch_gemm(P.pooled, lwf, lbf, nullptr, nullptr, (float*)d_out, nullptr, nullptr, GG, 384, 10);
}